// round 9
// baseline (speedup 1.0000x reference)
#include <cuda_runtime.h>
#include <cuda_bf16.h>
#include <cstdint>

#define N_NODES 50000
#define N_EDGES 800000
#define DF 256

typedef __nv_bfloat16 bf16;

// ---------------- device scratch ----------------
__device__ int   g_is64;
__device__ int   g_deg[N_NODES];
__device__ int   g_cursor[N_NODES];
__device__ int   g_rowstart[N_NODES + 1];
__device__ int   g_blocksum[64];
__device__ int   g_blockoff[64];
__device__ int   g_nbr[N_EDGES];
__device__ bf16  g_xh[(size_t)N_NODES * DF];
__device__ bf16  g_xl[(size_t)N_NODES * DF];
__device__ bf16  g_aggh[(size_t)N_NODES * DF];
__device__ bf16  g_aggl[(size_t)N_NODES * DF];
__device__ bf16  g_h1h[(size_t)N_NODES * DF];
__device__ bf16  g_h1l[(size_t)N_NODES * DF];
__device__ float g_h1f[(size_t)N_NODES * DF];
__device__ bf16  g_h2h[(size_t)N_NODES * DF];
__device__ bf16  g_h2l[(size_t)N_NODES * DF];
__device__ float g_hm[(size_t)N_NODES * DF];
__device__ bf16  g_wh[5][DF * DF];
__device__ bf16  g_wl[5][DF * DF];

__device__ __forceinline__ int edge_at(const void* edge, int idx) {
    if (g_is64) return (int)((const long long*)edge)[idx];
    return ((const int*)edge)[idx];
}

// ---------------- helpers ----------------
__device__ __forceinline__ uint32_t s2u(const void* p) {
    uint32_t a;
    asm("{ .reg .u64 t; cvta.to.shared.u64 t, %1; cvt.u32.u64 %0, t; }" : "=r"(a) : "l"(p));
    return a;
}
__device__ __forceinline__ uint32_t pack_bf16(float a, float b) {
    __nv_bfloat162 h = __floats2bfloat162_rn(a, b);
    return *reinterpret_cast<uint32_t*>(&h);
}

// ---------------- fp32 -> (hi, lo) bf16 pair split ----------------
__global__ void k_xsplit(const float* __restrict__ X, bf16* __restrict__ Xh,
                         bf16* __restrict__ Xl, int n8) {
    int i = blockIdx.x * blockDim.x + threadIdx.x;
    if (i >= n8) return;
    const float4* p = (const float4*)X + (size_t)i * 2;
    float4 v0 = __ldg(p), v1 = __ldg(p + 1);
    float f[8] = {v0.x, v0.y, v0.z, v0.w, v1.x, v1.y, v1.z, v1.w};
    float hf[8], lf[8];
    #pragma unroll
    for (int k = 0; k < 8; k++) {
        hf[k] = __bfloat162float(__float2bfloat16_rn(f[k]));
        lf[k] = f[k] - hf[k];
    }
    uint4 ho, lo;
    ho.x = pack_bf16(hf[0], hf[1]); ho.y = pack_bf16(hf[2], hf[3]);
    ho.z = pack_bf16(hf[4], hf[5]); ho.w = pack_bf16(hf[6], hf[7]);
    lo.x = pack_bf16(lf[0], lf[1]); lo.y = pack_bf16(lf[2], lf[3]);
    lo.z = pack_bf16(lf[4], lf[5]); lo.w = pack_bf16(lf[6], lf[7]);
    ((uint4*)Xh)[i] = ho;
    ((uint4*)Xl)[i] = lo;
}

// ---------------- weight pre-split ----------------
__global__ void k_wsplit(const float* __restrict__ w0, const float* __restrict__ w1,
                         const float* __restrict__ w2, const float* __restrict__ w3,
                         const float* __restrict__ w4) {
    int m = blockIdx.x >> 5;
    int i = (blockIdx.x & 31) * blockDim.x + threadIdx.x;
    const float* W = (m == 0) ? w0 : (m == 1) ? w1 : (m == 2) ? w2 : (m == 3) ? w3 : w4;
    const float4* p = (const float4*)W + (size_t)i * 2;
    float4 v0 = __ldg(p), v1 = __ldg(p + 1);
    float f[8] = {v0.x, v0.y, v0.z, v0.w, v1.x, v1.y, v1.z, v1.w};
    float hf[8], lf[8];
    #pragma unroll
    for (int k = 0; k < 8; k++) {
        hf[k] = __bfloat162float(__float2bfloat16_rn(f[k]));
        lf[k] = f[k] - hf[k];
    }
    uint4 ho, lo;
    ho.x = pack_bf16(hf[0], hf[1]); ho.y = pack_bf16(hf[2], hf[3]);
    ho.z = pack_bf16(hf[4], hf[5]); ho.w = pack_bf16(hf[6], hf[7]);
    lo.x = pack_bf16(lf[0], lf[1]); lo.y = pack_bf16(lf[2], lf[3]);
    lo.z = pack_bf16(lf[4], lf[5]); lo.w = pack_bf16(lf[6], lf[7]);
    ((uint4*)g_wh[m])[i] = ho;
    ((uint4*)g_wl[m])[i] = lo;
}

// ---------------- CSR build ----------------
__global__ void k_init(const void* edge) {
    int i = blockIdx.x * blockDim.x + threadIdx.x;
    if (i < N_NODES) { g_deg[i] = 0; g_cursor[i] = 0; }
    if (blockIdx.x == 0 && threadIdx.x == 0) {
        const long long* e = (const long long*)edge;
        int ok = 1;
        for (int j = 0; j < 16; j++) {
            long long v = e[j];
            if (v < 0 || v >= (long long)N_NODES) ok = 0;
        }
        g_is64 = ok;
    }
}

__global__ void k_count(const void* __restrict__ edge) {
    int e = blockIdx.x * blockDim.x + threadIdx.x;
    if (e >= N_EDGES) return;
    int dst = edge_at(edge, N_EDGES + e);
    atomicAdd(&g_deg[dst], 1);
}

__global__ void k_scanA() {
    __shared__ int ws[32];
    int b = blockIdx.x, t = threadIdx.x, lane = t & 31, w = t >> 5;
    int i = b * 1024 + t;
    int v = (i < N_NODES) ? g_deg[i] : 0;
    int sv = v;
    #pragma unroll
    for (int off = 1; off < 32; off <<= 1) {
        int x = __shfl_up_sync(0xffffffffu, sv, off);
        if (lane >= off) sv += x;
    }
    if (lane == 31) ws[w] = sv;
    __syncthreads();
    if (w == 0) {
        int s = ws[lane];
        #pragma unroll
        for (int off = 1; off < 32; off <<= 1) {
            int x = __shfl_up_sync(0xffffffffu, s, off);
            if (lane >= off) s += x;
        }
        ws[lane] = s;
    }
    __syncthreads();
    int tot = sv + ((w > 0) ? ws[w - 1] : 0);
    if (i < N_NODES) g_rowstart[i + 1] = tot;
    if (t == 1023) g_blocksum[b] = tot;
    if (b == 0 && t == 0) g_rowstart[0] = 0;
}

__global__ void k_scanB() {
    __shared__ int s[64];
    int t = threadIdx.x;
    s[t] = (t < 49) ? g_blocksum[t] : 0;
    __syncthreads();
    if (t == 0) {
        int acc = 0;
        for (int j = 0; j < 49; j++) { int x = s[j]; s[j] = acc; acc += x; }
    }
    __syncthreads();
    if (t < 49) g_blockoff[t] = s[t];
}

__global__ void k_scanC() {
    int b = blockIdx.x, t = threadIdx.x;
    int i = b * 1024 + t;
    if (i < N_NODES) g_rowstart[i + 1] += g_blockoff[b];
}

__global__ void k_fill(const void* __restrict__ edge) {
    int e = blockIdx.x * blockDim.x + threadIdx.x;
    if (e >= N_EDGES) return;
    int src = edge_at(edge, e);
    int dst = edge_at(edge, N_EDGES + e);
    int p = atomicAdd(&g_cursor[dst], 1);
    g_nbr[g_rowstart[dst] + p] = src;
}

// ---------------- mean aggregation: fp32 in, (hi,lo) pairs out ----------------
__global__ void k_aggregate(const float* __restrict__ X,
                            bf16* __restrict__ Oh, bf16* __restrict__ Ol) {
    int gw = (blockIdx.x * blockDim.x + threadIdx.x) >> 5;
    int lane = threadIdx.x & 31;
    if (gw >= N_NODES) return;
    int s = g_rowstart[gw], e = g_rowstart[gw + 1];
    float4 a0 = make_float4(0.f, 0.f, 0.f, 0.f);
    float4 a1 = make_float4(0.f, 0.f, 0.f, 0.f);
    int j = s;
    for (; j + 2 <= e; j += 2) {
        int s0 = g_nbr[j], s1 = g_nbr[j + 1];
        const float4* r0 = (const float4*)(X + (size_t)s0 * DF);
        const float4* r1 = (const float4*)(X + (size_t)s1 * DF);
        float4 u0 = __ldg(&r0[lane]);
        float4 u1 = __ldg(&r0[lane + 32]);
        float4 w0 = __ldg(&r1[lane]);
        float4 w1 = __ldg(&r1[lane + 32]);
        a0.x += u0.x + w0.x; a0.y += u0.y + w0.y;
        a0.z += u0.z + w0.z; a0.w += u0.w + w0.w;
        a1.x += u1.x + w1.x; a1.y += u1.y + w1.y;
        a1.z += u1.z + w1.z; a1.w += u1.w + w1.w;
    }
    if (j < e) {
        int s0 = g_nbr[j];
        const float4* r0 = (const float4*)(X + (size_t)s0 * DF);
        float4 u0 = __ldg(&r0[lane]);
        float4 u1 = __ldg(&r0[lane + 32]);
        a0.x += u0.x; a0.y += u0.y; a0.z += u0.z; a0.w += u0.w;
        a1.x += u1.x; a1.y += u1.y; a1.z += u1.z; a1.w += u1.w;
    }
    int cnt = e - s;
    float inv = 1.0f / (float)(cnt > 1 ? cnt : 1);
    float f[8] = {a0.x * inv, a0.y * inv, a0.z * inv, a0.w * inv,
                  a1.x * inv, a1.y * inv, a1.z * inv, a1.w * inv};
    float hf[8], lf[8];
    #pragma unroll
    for (int k = 0; k < 8; k++) {
        hf[k] = __bfloat162float(__float2bfloat16_rn(f[k]));
        lf[k] = f[k] - hf[k];
    }
    uint4 ho, lo;
    ho.x = pack_bf16(hf[0], hf[1]); ho.y = pack_bf16(hf[2], hf[3]);
    ho.z = pack_bf16(hf[4], hf[5]); ho.w = pack_bf16(hf[6], hf[7]);
    lo.x = pack_bf16(lf[0], lf[1]); lo.y = pack_bf16(lf[2], lf[3]);
    lo.z = pack_bf16(lf[4], lf[5]); lo.w = pack_bf16(lf[6], lf[7]);
    // interleave: first 4 uint32 (=8 elems each quad handled by layout below)
    uint4* oh = (uint4*)(Oh + (size_t)gw * DF);
    uint4* ol = (uint4*)(Ol + (size_t)gw * DF);
    // lane covers elems [lane*4 .. lane*4+3] and [128 + lane*4 ..]
    // f[0..3] correspond to a0 (elems lane*4..), f[4..7] to a1 (elems 128+lane*4..)
    uint2 h0 = make_uint2(ho.x, ho.y), h1 = make_uint2(ho.z, ho.w);
    uint2 l0 = make_uint2(lo.x, lo.y), l1 = make_uint2(lo.z, lo.w);
    ((uint2*)oh)[lane] = h0;
    ((uint2*)oh)[lane + 32] = h1;
    ((uint2*)ol)[lane] = l0;
    ((uint2*)ol)[lane + 32] = l1;
}

// ======================= cp.async mma.sync bf16 (3-term) GEMM =======================
// C = relu?( A1 @ W1^T [+ A2 @ W2^T] + bias ). All operands pre-split bf16 (hi,lo).
// acc += AhBh + AhBl + AlBh (fp32 acc). CTA 256(M) x 64(N), chunk K=32,
// 8 warps = 4(M) x 2(N), warp tile 64x32. 2-stage cp.async pipeline, 2 CTAs/SM.

#define S_AH 0
#define S_AL 20480
#define S_BH 40960
#define S_BL 46080
#define S_STG 51200
#define SMEM_GEMM (2 * S_STG)

__device__ __forceinline__ void cpa16(uint32_t dst, const void* src, int sz) {
    asm volatile("cp.async.cg.shared.global [%0], [%1], 16, %2;"
                 :: "r"(dst), "l"(src), "r"(sz) : "memory");
}
__device__ __forceinline__ void ldsm_x4(uint32_t* r, uint32_t addr) {
    asm volatile("ldmatrix.sync.aligned.m8n8.x4.shared.b16 {%0,%1,%2,%3}, [%4];"
                 : "=r"(r[0]), "=r"(r[1]), "=r"(r[2]), "=r"(r[3]) : "r"(addr));
}
__device__ __forceinline__ void mma16816(float* d, const uint32_t* a, uint32_t b0, uint32_t b1) {
    asm volatile(
        "mma.sync.aligned.m16n8k16.row.col.f32.bf16.bf16.f32 "
        "{%0,%1,%2,%3}, {%4,%5,%6,%7}, {%8,%9}, {%0,%1,%2,%3};"
        : "+f"(d[0]), "+f"(d[1]), "+f"(d[2]), "+f"(d[3])
        : "r"(a[0]), "r"(a[1]), "r"(a[2]), "r"(a[3]), "r"(b0), "r"(b1));
}

__global__ void __launch_bounds__(256, 2) k_gemm_mma(
    const bf16* __restrict__ A1h, const bf16* __restrict__ A1l,
    const bf16* __restrict__ W1h, const bf16* __restrict__ W1l,
    const bf16* __restrict__ A2h, const bf16* __restrict__ A2l,
    const bf16* __restrict__ W2h, const bf16* __restrict__ W2l,
    const float* __restrict__ bias,
    bf16* __restrict__ Ch, bf16* __restrict__ Cl, float* __restrict__ Cf,
    int M, int dual, int relu)
{
    extern __shared__ __align__(16) char smem[];
    uint32_t sb = s2u(smem);
    int tid = threadIdx.x, lane = tid & 31, wid = tid >> 5;
    int bm = blockIdx.x * 256, bn = blockIdx.y * 64;
    int wm = wid & 3, wn = wid >> 2;
    int nc = dual ? 16 : 8;

    float acc[4][4][4];
    #pragma unroll
    for (int mt = 0; mt < 4; mt++)
        #pragma unroll
        for (int nt = 0; nt < 4; nt++)
            #pragma unroll
            for (int j = 0; j < 4; j++) acc[mt][nt][j] = 0.f;

    int a_row = tid >> 2, a_q = tid & 3;       // issue mapping: 4 iters cover 256 rows
    int b_row = tid >> 2, b_q = tid & 3;       // 64 rows x 4 quads = 256 threads

    auto issue = [&](int c) {
        const bf16 *Ah, *Al, *Bh, *Bl;
        if (c >= 8) { Ah = A2h; Al = A2l; Bh = W2h; Bl = W2l; }
        else        { Ah = A1h; Al = A1l; Bh = W1h; Bl = W1l; }
        int kk = (c & 7) * 32;
        uint32_t st = sb + (c & 1) * S_STG;
        #pragma unroll
        for (int i = 0; i < 4; i++) {
            int row = a_row + i * 64;
            int grow = bm + row;
            int ok = (grow < M);
            size_t off = (size_t)(ok ? grow : (M - 1)) * DF + kk + a_q * 8;
            uint32_t d = st + S_AH + row * 80 + a_q * 16;
            cpa16(d, Ah + off, ok ? 16 : 0);
            cpa16(d + (S_AL - S_AH), Al + off, ok ? 16 : 0);
        }
        {
            size_t off = (size_t)(bn + b_row) * DF + kk + b_q * 8;
            uint32_t d = st + S_BH + b_row * 80 + b_q * 16;
            cpa16(d, Bh + off, 16);
            cpa16(d + (S_BL - S_BH), Bl + off, 16);
        }
    };

    issue(0);
    asm volatile("cp.async.commit_group;" ::: "memory");

    int ar = (lane & 15);
    int ac = (lane >> 4) << 3;
    int b_r0 = wn * 32 + (lane & 7) + ((lane >> 4) << 3);
    int b_c = ((lane >> 3) & 1) << 3;

    for (int c = 0; c < nc; c++) {
        asm volatile("cp.async.wait_group 0;" ::: "memory");
        __syncthreads();
        if (c + 1 < nc) {
            issue(c + 1);
            asm volatile("cp.async.commit_group;" ::: "memory");
        }
        uint32_t base = sb + (c & 1) * S_STG;
        #pragma unroll
        for (int ks = 0; ks < 2; ks++) {
            int kh = ks * 16;
            uint32_t bh[8], bl[8];
            #pragma unroll
            for (int h = 0; h < 2; h++) {
                uint32_t bd = base + S_BH + (b_r0 + h * 16) * 80 + (kh + b_c) * 2;
                ldsm_x4(bh + h * 4, bd);
                ldsm_x4(bl + h * 4, bd + (S_BL - S_BH));
            }
            #pragma unroll
            for (int mh = 0; mh < 2; mh++) {
                uint32_t ah[8], al[8];
                #pragma unroll
                for (int mt2 = 0; mt2 < 2; mt2++) {
                    uint32_t ad = base + S_AH +
                        (wm * 64 + mh * 32 + mt2 * 16 + ar) * 80 + (kh + ac) * 2;
                    ldsm_x4(ah + mt2 * 4, ad);
                    ldsm_x4(al + mt2 * 4, ad + (S_AL - S_AH));
                }
                #pragma unroll
                for (int mt2 = 0; mt2 < 2; mt2++)
                    #pragma unroll
                    for (int nt = 0; nt < 4; nt++) {
                        float* a = acc[mh * 2 + mt2][nt];
                        mma16816(a, ah + mt2 * 4, bh[nt * 2], bh[nt * 2 + 1]);
                        mma16816(a, ah + mt2 * 4, bl[nt * 2], bl[nt * 2 + 1]);
                        mma16816(a, al + mt2 * 4, bh[nt * 2], bh[nt * 2 + 1]);
                    }
            }
        }
    }

    // ---- epilogue: bias + relu; write (hi,lo) pairs and/or fp32 ----
    int g = lane >> 2, tg = lane & 3;
    #pragma unroll
    for (int mt = 0; mt < 4; mt++) {
        int r0 = bm + wm * 64 + mt * 16 + g;
        #pragma unroll
        for (int nt = 0; nt < 4; nt++) {
            int col = bn + wn * 32 + nt * 8 + tg * 2;
            float bx = __ldg(bias + col), by = __ldg(bias + col + 1);
            float2 v0, v1;
            v0.x = acc[mt][nt][0] + bx; v0.y = acc[mt][nt][1] + by;
            v1.x = acc[mt][nt][2] + bx; v1.y = acc[mt][nt][3] + by;
            if (relu) {
                v0.x = fmaxf(v0.x, 0.f); v0.y = fmaxf(v0.y, 0.f);
                v1.x = fmaxf(v1.x, 0.f); v1.y = fmaxf(v1.y, 0.f);
            }
            if (r0 < M) {
                if (Ch) {
                    float hx = __bfloat162float(__float2bfloat16_rn(v0.x));
                    float hy = __bfloat162float(__float2bfloat16_rn(v0.y));
                    *(uint32_t*)(Ch + (size_t)r0 * DF + col) = pack_bf16(hx, hy);
                    *(uint32_t*)(Cl + (size_t)r0 * DF + col) = pack_bf16(v0.x - hx, v0.y - hy);
                }
                if (Cf) *(float2*)(Cf + (size_t)r0 * DF + col) = v0;
            }
            if (r0 + 8 < M) {
                if (Ch) {
                    float hx = __bfloat162float(__float2bfloat16_rn(v1.x));
                    float hy = __bfloat162float(__float2bfloat16_rn(v1.y));
                    *(uint32_t*)(Ch + (size_t)(r0 + 8) * DF + col) = pack_bf16(hx, hy);
                    *(uint32_t*)(Cl + (size_t)(r0 + 8) * DF + col) = pack_bf16(v1.x - hx, v1.y - hy);
                }
                if (Cf) *(float2*)(Cf + (size_t)(r0 + 8) * DF + col) = v1;
            }
        }
    }
}

// ---------------- decoder: logits (8) + softmax, warp per node -------------
__global__ void __launch_bounds__(128) k_decoder(
    const float* __restrict__ H, const float* __restrict__ Wm2,
    const float* __restrict__ bm2, float* __restrict__ out)
{
    __shared__ float sW[8 * 256];
    int tid = threadIdx.x;
    #pragma unroll
    for (int i = 0; i < 16; i++) sW[tid + i * 128] = Wm2[tid + i * 128];
    __syncthreads();

    int lane = tid & 31, w = tid >> 5;
    int node = blockIdx.x * 4 + w;
    if (node >= N_NODES) return;

    float acc[8] = {0.f, 0.f, 0.f, 0.f, 0.f, 0.f, 0.f, 0.f};
    #pragma unroll
    for (int j = 0; j < 8; j++) {
        float v = H[(size_t)node * 256 + j * 32 + lane];
        #pragma unroll
        for (int o = 0; o < 8; o++)
            acc[o] = fmaf(v, sW[o * 256 + j * 32 + lane], acc[o]);
    }
    #pragma unroll
    for (int o = 0; o < 8; o++)
        #pragma unroll
        for (int off = 16; off >= 1; off >>= 1)
            acc[o] += __shfl_xor_sync(0xffffffffu, acc[o], off);

    if (lane < 8) {
        float logit = acc[lane] + bm2[lane];
        float m = logit;
        #pragma unroll
        for (int off = 4; off >= 1; off >>= 1)
            m = fmaxf(m, __shfl_xor_sync(0xffu, m, off));
        float ex = expf(logit - m);
        float ssum = ex;
        #pragma unroll
        for (int off = 4; off >= 1; off >>= 1)
            ssum += __shfl_xor_sync(0xffu, ssum, off);
        out[(size_t)node * 8 + lane] = ex / ssum;
    }
}

// ---------------- launch ----------------
extern "C" void kernel_launch(void* const* d_in, const int* in_sizes, int n_in,
                              void* d_out, int out_size) {
    const float* x    = (const float*)d_in[0];
    const void*  edge = d_in[1];
    const float* W1l = (const float*)d_in[2];
    const float* b1  = (const float*)d_in[3];
    const float* W1r = (const float*)d_in[4];
    const float* W2l = (const float*)d_in[5];
    const float* b2  = (const float*)d_in[6];
    const float* W2r = (const float*)d_in[7];
    const float* Wm1 = (const float*)d_in[8];
    const float* bm1 = (const float*)d_in[9];
    const float* Wm2 = (const float*)d_in[10];
    const float* bm2 = (const float*)d_in[11];
    float* out = (float*)d_out;

    bf16 *xh, *xl, *aggh, *aggl, *h1h, *h1l, *h2h, *h2l, *wh, *wl;
    float *h1f, *hm;
    cudaGetSymbolAddress((void**)&xh, g_xh);
    cudaGetSymbolAddress((void**)&xl, g_xl);
    cudaGetSymbolAddress((void**)&aggh, g_aggh);
    cudaGetSymbolAddress((void**)&aggl, g_aggl);
    cudaGetSymbolAddress((void**)&h1h, g_h1h);
    cudaGetSymbolAddress((void**)&h1l, g_h1l);
    cudaGetSymbolAddress((void**)&h1f, g_h1f);
    cudaGetSymbolAddress((void**)&h2h, g_h2h);
    cudaGetSymbolAddress((void**)&h2l, g_h2l);
    cudaGetSymbolAddress((void**)&hm, g_hm);
    cudaGetSymbolAddress((void**)&wh, g_wh);
    cudaGetSymbolAddress((void**)&wl, g_wl);

    cudaFuncSetAttribute(k_gemm_mma, cudaFuncAttributeMaxDynamicSharedMemorySize, SMEM_GEMM);

    int aggBlocks = (N_NODES * 32 + 255) / 256;
    dim3 gg((N_NODES + 255) / 256, 4);

    // pre-splits
    k_xsplit<<<(N_NODES * DF / 8 + 255) / 256, 256>>>(x, xh, xl, N_NODES * DF / 8);
    k_wsplit<<<160, 256>>>(W1l, W1r, W2l, W2r, Wm1);

    // CSR build
    k_init<<<(N_NODES + 255) / 256, 256>>>(edge);
    k_count<<<(N_EDGES + 255) / 256, 256>>>(edge);
    k_scanA<<<49, 1024>>>();
    k_scanB<<<1, 64>>>();
    k_scanC<<<49, 1024>>>();
    k_fill<<<(N_EDGES + 255) / 256, 256>>>(edge);

    // layer 1: h1 = relu(agg(x)@W1l + x@W1r + b1)  -> pairs + fp32
    k_aggregate<<<aggBlocks, 256>>>(x, aggh, aggl);
    k_gemm_mma<<<gg, 256, SMEM_GEMM>>>(aggh, aggl, wh + 0 * DF * DF, wl + 0 * DF * DF,
                                       xh, xl,     wh + 1 * DF * DF, wl + 1 * DF * DF,
                                       b1, h1h, h1l, h1f, N_NODES, 1, 1);

    // layer 2: h2 = relu(agg(h1)@W2l + h1@W2r + b2)  -> pairs only
    k_aggregate<<<aggBlocks, 256>>>(h1f, aggh, aggl);
    k_gemm_mma<<<gg, 256, SMEM_GEMM>>>(aggh, aggl, wh + 2 * DF * DF, wl + 2 * DF * DF,
                                       h1h, h1l,   wh + 3 * DF * DF, wl + 3 * DF * DF,
                                       b2, h2h, h2l, nullptr, N_NODES, 1, 1);

    // MLP hidden: hm = relu(h2@Wm1 + bm1)  -> fp32 only
    k_gemm_mma<<<gg, 256, SMEM_GEMM>>>(h2h, h2l, wh + 4 * DF * DF, wl + 4 * DF * DF,
                                       nullptr, nullptr, wh + 4 * DF * DF, wl + 4 * DF * DF,
                                       bm1, nullptr, nullptr, hm, N_NODES, 0, 1);

    // decoder + softmax
    k_decoder<<<(N_NODES + 3) / 4, 128>>>(hm, Wm2, bm2, out);
}

// round 10
// speedup vs baseline: 1.1115x; 1.1115x over previous
#include <cuda_runtime.h>
#include <cuda_bf16.h>
#include <cstdint>

#define N_NODES 50000
#define N_EDGES 800000
#define DF 256

typedef __nv_bfloat16 bf16;

// ---------------- device scratch ----------------
__device__ int   g_is64;
__device__ int   g_deg[N_NODES];
__device__ int   g_cursor[N_NODES];
__device__ int   g_rowstart[N_NODES + 1];
__device__ int   g_blocksum[64];
__device__ int   g_blockoff[64];
__device__ int   g_nbr[N_EDGES];
__device__ float g_agg[(size_t)N_NODES * DF];
__device__ float g_h1[(size_t)N_NODES * DF];
__device__ float g_h2[(size_t)N_NODES * DF];
__device__ bf16  g_xb[(size_t)N_NODES * DF];
__device__ bf16  g_h1b[(size_t)N_NODES * DF];
__device__ bf16  g_wh[5][DF * DF];
__device__ bf16  g_wl[5][DF * DF];

__device__ __forceinline__ int edge_at(const void* edge, int idx) {
    if (g_is64) return (int)((const long long*)edge)[idx];
    return ((const int*)edge)[idx];
}

// ---------------- helpers ----------------
__device__ __forceinline__ uint32_t s2u(const void* p) {
    uint32_t a;
    asm("{ .reg .u64 t; cvta.to.shared.u64 t, %1; cvt.u32.u64 %0, t; }" : "=r"(a) : "l"(p));
    return a;
}
__device__ __forceinline__ uint32_t pack_bf16(float a, float b) {
    __nv_bfloat162 h = __floats2bfloat162_rn(a, b);
    return *reinterpret_cast<uint32_t*>(&h);
}

// ---------------- fp32 -> bf16 row copy (for aggregation gather) ----------------
__global__ void k_tob16(const float* __restrict__ X, bf16* __restrict__ Xb, int n8) {
    int i = blockIdx.x * blockDim.x + threadIdx.x;
    if (i >= n8) return;
    const float4* p = (const float4*)X + (size_t)i * 2;
    float4 v0 = __ldg(p), v1 = __ldg(p + 1);
    uint4 o;
    o.x = pack_bf16(v0.x, v0.y); o.y = pack_bf16(v0.z, v0.w);
    o.z = pack_bf16(v1.x, v1.y); o.w = pack_bf16(v1.z, v1.w);
    ((uint4*)Xb)[i] = o;
}

// ---------------- weight pre-split: 5 matrices, one launch ----------------
__global__ void k_wsplit(const float* __restrict__ w0, const float* __restrict__ w1,
                         const float* __restrict__ w2, const float* __restrict__ w3,
                         const float* __restrict__ w4) {
    int m = blockIdx.x >> 5;
    int i = (blockIdx.x & 31) * blockDim.x + threadIdx.x;
    const float* W = (m == 0) ? w0 : (m == 1) ? w1 : (m == 2) ? w2 : (m == 3) ? w3 : w4;
    const float4* p = (const float4*)W + (size_t)i * 2;
    float4 v0 = __ldg(p), v1 = __ldg(p + 1);
    float f[8] = {v0.x, v0.y, v0.z, v0.w, v1.x, v1.y, v1.z, v1.w};
    float hf[8], lf[8];
    #pragma unroll
    for (int k = 0; k < 8; k++) {
        hf[k] = __bfloat162float(__float2bfloat16_rn(f[k]));
        lf[k] = f[k] - hf[k];
    }
    uint4 ho, lo;
    ho.x = pack_bf16(hf[0], hf[1]); ho.y = pack_bf16(hf[2], hf[3]);
    ho.z = pack_bf16(hf[4], hf[5]); ho.w = pack_bf16(hf[6], hf[7]);
    lo.x = pack_bf16(lf[0], lf[1]); lo.y = pack_bf16(lf[2], lf[3]);
    lo.z = pack_bf16(lf[4], lf[5]); lo.w = pack_bf16(lf[6], lf[7]);
    ((uint4*)g_wh[m])[i] = ho;
    ((uint4*)g_wl[m])[i] = lo;
}

// ---------------- CSR build ----------------
__global__ void k_init(const void* edge) {
    int i = blockIdx.x * blockDim.x + threadIdx.x;
    if (i < N_NODES) { g_deg[i] = 0; g_cursor[i] = 0; }
    if (blockIdx.x == 0 && threadIdx.x == 0) {
        const long long* e = (const long long*)edge;
        int ok = 1;
        for (int j = 0; j < 16; j++) {
            long long v = e[j];
            if (v < 0 || v >= (long long)N_NODES) ok = 0;
        }
        g_is64 = ok;
    }
}

__global__ void k_count(const void* __restrict__ edge) {
    int e = blockIdx.x * blockDim.x + threadIdx.x;
    if (e >= N_EDGES) return;
    int dst = edge_at(edge, N_EDGES + e);
    atomicAdd(&g_deg[dst], 1);
}

__global__ void k_scanA() {
    __shared__ int ws[32];
    int b = blockIdx.x, t = threadIdx.x, lane = t & 31, w = t >> 5;
    int i = b * 1024 + t;
    int v = (i < N_NODES) ? g_deg[i] : 0;
    int sv = v;
    #pragma unroll
    for (int off = 1; off < 32; off <<= 1) {
        int x = __shfl_up_sync(0xffffffffu, sv, off);
        if (lane >= off) sv += x;
    }
    if (lane == 31) ws[w] = sv;
    __syncthreads();
    if (w == 0) {
        int s = ws[lane];
        #pragma unroll
        for (int off = 1; off < 32; off <<= 1) {
            int x = __shfl_up_sync(0xffffffffu, s, off);
            if (lane >= off) s += x;
        }
        ws[lane] = s;
    }
    __syncthreads();
    int tot = sv + ((w > 0) ? ws[w - 1] : 0);
    if (i < N_NODES) g_rowstart[i + 1] = tot;
    if (t == 1023) g_blocksum[b] = tot;
    if (b == 0 && t == 0) g_rowstart[0] = 0;
}

__global__ void k_scanB() {
    __shared__ int s[64];
    int t = threadIdx.x;
    s[t] = (t < 49) ? g_blocksum[t] : 0;
    __syncthreads();
    if (t == 0) {
        int acc = 0;
        for (int j = 0; j < 49; j++) { int x = s[j]; s[j] = acc; acc += x; }
    }
    __syncthreads();
    if (t < 49) g_blockoff[t] = s[t];
}

__global__ void k_scanC() {
    int b = blockIdx.x, t = threadIdx.x;
    int i = b * 1024 + t;
    if (i < N_NODES) g_rowstart[i + 1] += g_blockoff[b];
}

__global__ void k_fill(const void* __restrict__ edge) {
    int e = blockIdx.x * blockDim.x + threadIdx.x;
    if (e >= N_EDGES) return;
    int src = edge_at(edge, e);
    int dst = edge_at(edge, N_EDGES + e);
    int p = atomicAdd(&g_cursor[dst], 1);
    g_nbr[g_rowstart[dst] + p] = src;
}

// ---------------- mean aggregation: warp per node, bf16 gather, fp32 out ----------------
__global__ void k_aggregate(const bf16* __restrict__ Xb, float* __restrict__ out) {
    int gw = (blockIdx.x * blockDim.x + threadIdx.x) >> 5;
    int lane = threadIdx.x & 31;
    if (gw >= N_NODES) return;
    int s = g_rowstart[gw], e = g_rowstart[gw + 1];
    float acc[8] = {0.f, 0.f, 0.f, 0.f, 0.f, 0.f, 0.f, 0.f};
    int j = s;
    for (; j + 2 <= e; j += 2) {
        int s0 = g_nbr[j], s1 = g_nbr[j + 1];
        uint4 u = __ldg((const uint4*)(Xb + (size_t)s0 * DF) + lane);
        uint4 w = __ldg((const uint4*)(Xb + (size_t)s1 * DF) + lane);
        const __nv_bfloat162* up = (const __nv_bfloat162*)&u;
        const __nv_bfloat162* wp = (const __nv_bfloat162*)&w;
        #pragma unroll
        for (int i = 0; i < 4; i++) {
            float2 a = __bfloat1622float2(up[i]);
            float2 b = __bfloat1622float2(wp[i]);
            acc[2 * i]     += a.x + b.x;
            acc[2 * i + 1] += a.y + b.y;
        }
    }
    if (j < e) {
        int s0 = g_nbr[j];
        uint4 u = __ldg((const uint4*)(Xb + (size_t)s0 * DF) + lane);
        const __nv_bfloat162* up = (const __nv_bfloat162*)&u;
        #pragma unroll
        for (int i = 0; i < 4; i++) {
            float2 a = __bfloat1622float2(up[i]);
            acc[2 * i]     += a.x;
            acc[2 * i + 1] += a.y;
        }
    }
    int cnt = e - s;
    float inv = 1.0f / (float)(cnt > 1 ? cnt : 1);
    // lane covers row elements [lane*8 .. lane*8+7]
    float4 o0 = make_float4(acc[0] * inv, acc[1] * inv, acc[2] * inv, acc[3] * inv);
    float4 o1 = make_float4(acc[4] * inv, acc[5] * inv, acc[6] * inv, acc[7] * inv);
    float4* o = (float4*)(out + (size_t)gw * DF);
    o[lane * 2]     = o0;
    o[lane * 2 + 1] = o1;
}

// ======================= mma.sync bf16 (3-term split) GEMM =======================
// C = relu?( A1 @ W1^T [+ A2 @ W2^T] + bias ). A fp32 (split in-kernel),
// W pre-split bf16 (hi, lo). acc += AhBh + AhBl + AlBh (fp32 acc).
// CTA 128(M) x 64(N), chunk K=32, double-buffered smem, 2 CTAs/SM.  [R6-proven]

#define S_AH 0
#define S_AL 10240
#define S_BH 20480
#define S_BL 25600
#define S_BUF 30720
#define SMEM_GEMM (2 * S_BUF)

__device__ __forceinline__ void ldsm_x4(uint32_t* r, uint32_t addr) {
    asm volatile("ldmatrix.sync.aligned.m8n8.x4.shared.b16 {%0,%1,%2,%3}, [%4];"
                 : "=r"(r[0]), "=r"(r[1]), "=r"(r[2]), "=r"(r[3]) : "r"(addr));
}
__device__ __forceinline__ void mma16816(float* d, const uint32_t* a, uint32_t b0, uint32_t b1) {
    asm volatile(
        "mma.sync.aligned.m16n8k16.row.col.f32.bf16.bf16.f32 "
        "{%0,%1,%2,%3}, {%4,%5,%6,%7}, {%8,%9}, {%0,%1,%2,%3};"
        : "+f"(d[0]), "+f"(d[1]), "+f"(d[2]), "+f"(d[3])
        : "r"(a[0]), "r"(a[1]), "r"(a[2]), "r"(a[3]), "r"(b0), "r"(b1));
}

__global__ void __launch_bounds__(256, 2) k_gemm_mma(
    const float* __restrict__ A1,
    const bf16* __restrict__ W1h, const bf16* __restrict__ W1l,
    const float* __restrict__ A2,
    const bf16* __restrict__ W2h, const bf16* __restrict__ W2l,
    const float* __restrict__ bias, float* __restrict__ C,
    bf16* __restrict__ Cb,
    int M, int dual, int relu)
{
    extern __shared__ __align__(16) char smem[];
    uint32_t sb = s2u(smem);
    int tid = threadIdx.x, lane = tid & 31, wid = tid >> 5;
    int bm = blockIdx.x * 128, bn = blockIdx.y * 64;
    int wm = wid & 3, wn = wid >> 2;

    float acc[2][4][4];
    #pragma unroll
    for (int mt = 0; mt < 2; mt++)
        #pragma unroll
        for (int nt = 0; nt < 4; nt++)
            #pragma unroll
            for (int j = 0; j < 4; j++) acc[mt][nt][j] = 0.f;

    int nc = dual ? 16 : 8;
    float4 av[4];
    uint4 bvh, bvl;
    int b_n = tid >> 2, b_c16 = tid & 3;

    auto gload = [&](int c) {
        const float* A = (c >= 8) ? A2 : A1;
        const bf16* Bh = (c >= 8) ? W2h : W1h;
        const bf16* Bl = (c >= 8) ? W2l : W1l;
        int kk = (c & 7) * 32;
        #pragma unroll
        for (int i = 0; i < 4; i++) {
            int f = tid + i * 256, row = f >> 3, cc = f & 7;
            int grow = bm + row;
            av[i] = (grow < M) ? __ldg((const float4*)(A + (size_t)grow * 256 + kk + cc * 4))
                               : make_float4(0.f, 0.f, 0.f, 0.f);
        }
        size_t boff = (size_t)(bn + b_n) * DF + kk + b_c16 * 8;
        bvh = __ldg((const uint4*)(Bh + boff));
        bvl = __ldg((const uint4*)(Bl + boff));
    };

    auto sstore = [&](int buf) {
        char* st = smem + buf * S_BUF;
        #pragma unroll
        for (int i = 0; i < 4; i++) {
            int f = tid + i * 256, row = f >> 3, cc = f & 7;
            float4 v = av[i];
            float hx = __bfloat162float(__float2bfloat16_rn(v.x));
            float hy = __bfloat162float(__float2bfloat16_rn(v.y));
            float hz = __bfloat162float(__float2bfloat16_rn(v.z));
            float hw = __bfloat162float(__float2bfloat16_rn(v.w));
            uint2 hi = make_uint2(pack_bf16(hx, hy), pack_bf16(hz, hw));
            uint2 lo = make_uint2(pack_bf16(v.x - hx, v.y - hy), pack_bf16(v.z - hz, v.w - hw));
            *(uint2*)(st + S_AH + row * 80 + cc * 8) = hi;
            *(uint2*)(st + S_AL + row * 80 + cc * 8) = lo;
        }
        *(uint4*)(st + S_BH + b_n * 80 + b_c16 * 16) = bvh;
        *(uint4*)(st + S_BL + b_n * 80 + b_c16 * 16) = bvl;
    };

    gload(0);
    sstore(0);
    __syncthreads();

    for (int c = 0; c < nc; c++) {
        int buf = c & 1;
        if (c + 1 < nc) gload(c + 1);

        uint32_t base = sb + buf * S_BUF;
        int a_row = wm * 32 + (lane & 15);
        int a_col = (lane >> 4) << 3;
        int b_row0 = wn * 32 + (lane & 7) + ((lane >> 4) << 3);
        int b_col = ((lane >> 3) & 1) << 3;

        #pragma unroll
        for (int ks = 0; ks < 2; ks++) {
            int kh = ks * 16;
            uint32_t ah[8], al[8], bh[8], bl[8];
            #pragma unroll
            for (int mt = 0; mt < 2; mt++) {
                uint32_t ad = base + S_AH + (a_row + mt * 16) * 80 + (kh + a_col) * 2;
                ldsm_x4(ah + mt * 4, ad);
                ldsm_x4(al + mt * 4, ad + (S_AL - S_AH));
            }
            #pragma unroll
            for (int h = 0; h < 2; h++) {
                uint32_t bd = base + S_BH + (b_row0 + h * 16) * 80 + (kh + b_col) * 2;
                ldsm_x4(bh + h * 4, bd);
                ldsm_x4(bl + h * 4, bd + (S_BL - S_BH));
            }
            #pragma unroll
            for (int mt = 0; mt < 2; mt++)
                #pragma unroll
                for (int nt = 0; nt < 4; nt++) {
                    mma16816(acc[mt][nt], ah + mt * 4, bh[nt * 2], bh[nt * 2 + 1]);
                    mma16816(acc[mt][nt], ah + mt * 4, bl[nt * 2], bl[nt * 2 + 1]);
                    mma16816(acc[mt][nt], al + mt * 4, bh[nt * 2], bh[nt * 2 + 1]);
                }
        }
        if (c + 1 < nc) sstore((c + 1) & 1);
        __syncthreads();
    }

    // ---- epilogue: bias + relu, write fp32 C (+ optional bf16 Cb) ----
    int g = lane >> 2, tg = lane & 3;
    #pragma unroll
    for (int mt = 0; mt < 2; mt++) {
        int r0 = bm + wm * 32 + mt * 16 + g;
        #pragma unroll
        for (int nt = 0; nt < 4; nt++) {
            int col = bn + wn * 32 + nt * 8 + tg * 2;
            float bx = __ldg(bias + col), by = __ldg(bias + col + 1);
            float2 v0, v1;
            v0.x = acc[mt][nt][0] + bx; v0.y = acc[mt][nt][1] + by;
            v1.x = acc[mt][nt][2] + bx; v1.y = acc[mt][nt][3] + by;
            if (relu) {
                v0.x = fmaxf(v0.x, 0.f); v0.y = fmaxf(v0.y, 0.f);
                v1.x = fmaxf(v1.x, 0.f); v1.y = fmaxf(v1.y, 0.f);
            }
            if (r0 < M) {
                *(float2*)(C + (size_t)r0 * 256 + col) = v0;
                if (Cb) *(uint32_t*)(Cb + (size_t)r0 * 256 + col) = pack_bf16(v0.x, v0.y);
            }
            if (r0 + 8 < M) {
                *(float2*)(C + (size_t)(r0 + 8) * 256 + col) = v1;
                if (Cb) *(uint32_t*)(Cb + (size_t)(r0 + 8) * 256 + col) = pack_bf16(v1.x, v1.y);
            }
        }
    }
}

// ---------------- decoder: logits (8) + softmax, warp per node -------------
__global__ void __launch_bounds__(128) k_decoder(
    const float* __restrict__ H, const float* __restrict__ Wm2,
    const float* __restrict__ bm2, float* __restrict__ out)
{
    __shared__ float sW[8 * 256];
    int tid = threadIdx.x;
    #pragma unroll
    for (int i = 0; i < 16; i++) sW[tid + i * 128] = Wm2[tid + i * 128];
    __syncthreads();

    int lane = tid & 31, w = tid >> 5;
    int node = blockIdx.x * 4 + w;
    if (node >= N_NODES) return;

    float acc[8] = {0.f, 0.f, 0.f, 0.f, 0.f, 0.f, 0.f, 0.f};
    #pragma unroll
    for (int j = 0; j < 8; j++) {
        float v = H[(size_t)node * 256 + j * 32 + lane];
        #pragma unroll
        for (int o = 0; o < 8; o++)
            acc[o] = fmaf(v, sW[o * 256 + j * 32 + lane], acc[o]);
    }
    #pragma unroll
    for (int o = 0; o < 8; o++)
        #pragma unroll
        for (int off = 16; off >= 1; off >>= 1)
            acc[o] += __shfl_xor_sync(0xffffffffu, acc[o], off);

    if (lane < 8) {
        float logit = acc[lane] + bm2[lane];
        float m = logit;
        #pragma unroll
        for (int off = 4; off >= 1; off >>= 1)
            m = fmaxf(m, __shfl_xor_sync(0xffu, m, off));
        float ex = expf(logit - m);
        float ssum = ex;
        #pragma unroll
        for (int off = 4; off >= 1; off >>= 1)
            ssum += __shfl_xor_sync(0xffu, ssum, off);
        out[(size_t)node * 8 + lane] = ex / ssum;
    }
}

// ---------------- launch ----------------
extern "C" void kernel_launch(void* const* d_in, const int* in_sizes, int n_in,
                              void* d_out, int out_size) {
    const float* x    = (const float*)d_in[0];
    const void*  edge = d_in[1];
    const float* W1l = (const float*)d_in[2];
    const float* b1  = (const float*)d_in[3];
    const float* W1r = (const float*)d_in[4];
    const float* W2l = (const float*)d_in[5];
    const float* b2  = (const float*)d_in[6];
    const float* W2r = (const float*)d_in[7];
    const float* Wm1 = (const float*)d_in[8];
    const float* bm1 = (const float*)d_in[9];
    const float* Wm2 = (const float*)d_in[10];
    const float* bm2 = (const float*)d_in[11];
    float* out = (float*)d_out;

    float *agg, *h1, *h2;
    bf16 *wh, *wl, *xb, *h1b;
    cudaGetSymbolAddress((void**)&agg, g_agg);
    cudaGetSymbolAddress((void**)&h1, g_h1);
    cudaGetSymbolAddress((void**)&h2, g_h2);
    cudaGetSymbolAddress((void**)&xb, g_xb);
    cudaGetSymbolAddress((void**)&h1b, g_h1b);
    cudaGetSymbolAddress((void**)&wh, g_wh);
    cudaGetSymbolAddress((void**)&wl, g_wl);

    cudaFuncSetAttribute(k_gemm_mma, cudaFuncAttributeMaxDynamicSharedMemorySize, SMEM_GEMM);

    // weight pre-split + x bf16 copy
    k_wsplit<<<160, 256>>>(W1l, W1r, W2l, W2r, Wm1);
    k_tob16<<<(N_NODES * DF / 8 + 255) / 256, 256>>>(x, xb, N_NODES * DF / 8);

    // CSR build
    k_init<<<(N_NODES + 255) / 256, 256>>>(edge);
    k_count<<<(N_EDGES + 255) / 256, 256>>>(edge);
    k_scanA<<<49, 1024>>>();
    k_scanB<<<1, 64>>>();
    k_scanC<<<49, 1024>>>();
    k_fill<<<(N_EDGES + 255) / 256, 256>>>(edge);

    int aggBlocks = (N_NODES * 32 + 255) / 256;
    dim3 gg((N_NODES + 127) / 128, 4);

    // layer 1: h1 = relu(agg(x)@W1l + x@W1r + b1); also emit h1b (bf16)
    k_aggregate<<<aggBlocks, 256>>>(xb, agg);
    k_gemm_mma<<<gg, 256, SMEM_GEMM>>>(agg, wh + 0 * DF * DF, wl + 0 * DF * DF,
                                       x,   wh + 1 * DF * DF, wl + 1 * DF * DF,
                                       b1, h1, h1b, N_NODES, 1, 1);

    // layer 2: h2 = relu(agg(h1)@W2l + h1@W2r + b2)
    k_aggregate<<<aggBlocks, 256>>>(h1b, agg);
    k_gemm_mma<<<gg, 256, SMEM_GEMM>>>(agg, wh + 2 * DF * DF, wl + 2 * DF * DF,
                                       h1,  wh + 3 * DF * DF, wl + 3 * DF * DF,
                                       b2, h2, nullptr, N_NODES, 1, 1);

    // MLP hidden (reuse h1)
    k_gemm_mma<<<gg, 256, SMEM_GEMM>>>(h2, wh + 4 * DF * DF, wl + 4 * DF * DF,
                                       nullptr, wh + 4 * DF * DF, wl + 4 * DF * DF,
                                       bm1, h1, nullptr, N_NODES, 0, 1);

    // decoder + softmax
    k_decoder<<<(N_NODES + 3) / 4, 128>>>(h1, Wm2, bm2, out);
}

// round 11
// speedup vs baseline: 1.2338x; 1.1100x over previous
#include <cuda_runtime.h>
#include <cuda_fp16.h>
#include <cstdint>

#define N_NODES 50000
#define N_EDGES 800000
#define DF 256

// ---------------- device scratch ----------------
__device__ int    g_is64;
__device__ int    g_deg[N_NODES];
__device__ int    g_cursor[N_NODES];
__device__ int    g_rowstart[N_NODES + 1];
__device__ int    g_blocksum[64];
__device__ int    g_blockoff[64];
__device__ int    g_nbr[N_EDGES];
__device__ float  g_agg[(size_t)N_NODES * DF];
__device__ float  g_h1[(size_t)N_NODES * DF];
__device__ float  g_h2[(size_t)N_NODES * DF];
__device__ __half g_xb[(size_t)N_NODES * DF];
__device__ __half g_h1b[(size_t)N_NODES * DF];
__device__ __half g_wh[5][DF * DF];
__device__ __half g_wl[5][DF * DF];

__device__ __forceinline__ int edge_at(const void* edge, int idx) {
    if (g_is64) return (int)((const long long*)edge)[idx];
    return ((const int*)edge)[idx];
}

// ---------------- helpers ----------------
__device__ __forceinline__ uint32_t s2u(const void* p) {
    uint32_t a;
    asm("{ .reg .u64 t; cvta.to.shared.u64 t, %1; cvt.u32.u64 %0, t; }" : "=r"(a) : "l"(p));
    return a;
}
__device__ __forceinline__ uint32_t pack_f16(float a, float b) {
    __half2 h = __floats2half2_rn(a, b);
    return *reinterpret_cast<uint32_t*>(&h);
}

// ---------------- fp32 -> fp16 row copy (for aggregation gather) ----------------
__global__ void k_tof16(const float* __restrict__ X, __half* __restrict__ Xb, int n8) {
    int i = blockIdx.x * blockDim.x + threadIdx.x;
    if (i >= n8) return;
    const float4* p = (const float4*)X + (size_t)i * 2;
    float4 v0 = __ldg(p), v1 = __ldg(p + 1);
    uint4 o;
    o.x = pack_f16(v0.x, v0.y); o.y = pack_f16(v0.z, v0.w);
    o.z = pack_f16(v1.x, v1.y); o.w = pack_f16(v1.z, v1.w);
    ((uint4*)Xb)[i] = o;
}

// ---------------- weight pre-split (fp16 hi/lo): 5 matrices, one launch ----------------
__global__ void k_wsplit(const float* __restrict__ w0, const float* __restrict__ w1,
                         const float* __restrict__ w2, const float* __restrict__ w3,
                         const float* __restrict__ w4) {
    int m = blockIdx.x >> 5;
    int i = (blockIdx.x & 31) * blockDim.x + threadIdx.x;
    const float* W = (m == 0) ? w0 : (m == 1) ? w1 : (m == 2) ? w2 : (m == 3) ? w3 : w4;
    const float4* p = (const float4*)W + (size_t)i * 2;
    float4 v0 = __ldg(p), v1 = __ldg(p + 1);
    float f[8] = {v0.x, v0.y, v0.z, v0.w, v1.x, v1.y, v1.z, v1.w};
    float hf[8], lf[8];
    #pragma unroll
    for (int k = 0; k < 8; k++) {
        hf[k] = __half2float(__float2half_rn(f[k]));
        lf[k] = f[k] - hf[k];
    }
    uint4 ho, lo;
    ho.x = pack_f16(hf[0], hf[1]); ho.y = pack_f16(hf[2], hf[3]);
    ho.z = pack_f16(hf[4], hf[5]); ho.w = pack_f16(hf[6], hf[7]);
    lo.x = pack_f16(lf[0], lf[1]); lo.y = pack_f16(lf[2], lf[3]);
    lo.z = pack_f16(lf[4], lf[5]); lo.w = pack_f16(lf[6], lf[7]);
    ((uint4*)g_wh[m])[i] = ho;
    ((uint4*)g_wl[m])[i] = lo;
}

// ---------------- CSR build ----------------
__global__ void k_init(const void* edge) {
    int i = blockIdx.x * blockDim.x + threadIdx.x;
    if (i < N_NODES) { g_deg[i] = 0; g_cursor[i] = 0; }
    if (blockIdx.x == 0 && threadIdx.x == 0) {
        const long long* e = (const long long*)edge;
        int ok = 1;
        for (int j = 0; j < 16; j++) {
            long long v = e[j];
            if (v < 0 || v >= (long long)N_NODES) ok = 0;
        }
        g_is64 = ok;
    }
}

__global__ void k_count(const void* __restrict__ edge) {
    int e = blockIdx.x * blockDim.x + threadIdx.x;
    if (e >= N_EDGES) return;
    int dst = edge_at(edge, N_EDGES + e);
    atomicAdd(&g_deg[dst], 1);
}

__global__ void k_scanA() {
    __shared__ int ws[32];
    int b = blockIdx.x, t = threadIdx.x, lane = t & 31, w = t >> 5;
    int i = b * 1024 + t;
    int v = (i < N_NODES) ? g_deg[i] : 0;
    int sv = v;
    #pragma unroll
    for (int off = 1; off < 32; off <<= 1) {
        int x = __shfl_up_sync(0xffffffffu, sv, off);
        if (lane >= off) sv += x;
    }
    if (lane == 31) ws[w] = sv;
    __syncthreads();
    if (w == 0) {
        int s = ws[lane];
        #pragma unroll
        for (int off = 1; off < 32; off <<= 1) {
            int x = __shfl_up_sync(0xffffffffu, s, off);
            if (lane >= off) s += x;
        }
        ws[lane] = s;
    }
    __syncthreads();
    int tot = sv + ((w > 0) ? ws[w - 1] : 0);
    if (i < N_NODES) g_rowstart[i + 1] = tot;
    if (t == 1023) g_blocksum[b] = tot;
    if (b == 0 && t == 0) g_rowstart[0] = 0;
}

__global__ void k_scanB() {
    __shared__ int s[64];
    int t = threadIdx.x;
    s[t] = (t < 49) ? g_blocksum[t] : 0;
    __syncthreads();
    if (t == 0) {
        int acc = 0;
        for (int j = 0; j < 49; j++) { int x = s[j]; s[j] = acc; acc += x; }
    }
    __syncthreads();
    if (t < 49) g_blockoff[t] = s[t];
}

__global__ void k_scanC() {
    int b = blockIdx.x, t = threadIdx.x;
    int i = b * 1024 + t;
    if (i < N_NODES) g_rowstart[i + 1] += g_blockoff[b];
}

__global__ void k_fill(const void* __restrict__ edge) {
    int e = blockIdx.x * blockDim.x + threadIdx.x;
    if (e >= N_EDGES) return;
    int src = edge_at(edge, e);
    int dst = edge_at(edge, N_EDGES + e);
    int p = atomicAdd(&g_cursor[dst], 1);
    g_nbr[g_rowstart[dst] + p] = src;
}

// ---------------- mean aggregation: warp per node, fp16 gather, fp32 out ----------------
__global__ void k_aggregate(const __half* __restrict__ Xb, float* __restrict__ out) {
    int gw = (blockIdx.x * blockDim.x + threadIdx.x) >> 5;
    int lane = threadIdx.x & 31;
    if (gw >= N_NODES) return;
    int s = g_rowstart[gw], e = g_rowstart[gw + 1];
    float acc[8] = {0.f, 0.f, 0.f, 0.f, 0.f, 0.f, 0.f, 0.f};
    int j = s;
    for (; j + 2 <= e; j += 2) {
        int s0 = g_nbr[j], s1 = g_nbr[j + 1];
        uint4 u = __ldg((const uint4*)(Xb + (size_t)s0 * DF) + lane);
        uint4 w = __ldg((const uint4*)(Xb + (size_t)s1 * DF) + lane);
        const __half2* up = (const __half2*)&u;
        const __half2* wp = (const __half2*)&w;
        #pragma unroll
        for (int i = 0; i < 4; i++) {
            float2 a = __half22float2(up[i]);
            float2 b = __half22float2(wp[i]);
            acc[2 * i]     += a.x + b.x;
            acc[2 * i + 1] += a.y + b.y;
        }
    }
    if (j < e) {
        int s0 = g_nbr[j];
        uint4 u = __ldg((const uint4*)(Xb + (size_t)s0 * DF) + lane);
        const __half2* up = (const __half2*)&u;
        #pragma unroll
        for (int i = 0; i < 4; i++) {
            float2 a = __half22float2(up[i]);
            acc[2 * i]     += a.x;
            acc[2 * i + 1] += a.y;
        }
    }
    int cnt = e - s;
    float inv = 1.0f / (float)(cnt > 1 ? cnt : 1);
    float4 o0 = make_float4(acc[0] * inv, acc[1] * inv, acc[2] * inv, acc[3] * inv);
    float4 o1 = make_float4(acc[4] * inv, acc[5] * inv, acc[6] * inv, acc[7] * inv);
    float4* o = (float4*)(out + (size_t)gw * DF);
    o[lane * 2]     = o0;
    o[lane * 2 + 1] = o1;
}

// ======================= mma.sync fp16 (2-term split) GEMM =======================
// C = relu?( A1 @ W1^T [+ A2 @ W2^T] + bias ). A fp32 -> fp16 in-kernel (single),
// W pre-split fp16 (hi, lo). acc += A*Bh + A*Bl (fp32 acc).
// CTA 128(M) x 64(N), chunk K=32, double-buffered smem, 2 CTAs/SM.  [R6 structure]

#define S_AH 0
#define S_BH 10240
#define S_BL 15360
#define S_BUF 20480
#define SMEM_GEMM (2 * S_BUF)

__device__ __forceinline__ void ldsm_x4(uint32_t* r, uint32_t addr) {
    asm volatile("ldmatrix.sync.aligned.m8n8.x4.shared.b16 {%0,%1,%2,%3}, [%4];"
                 : "=r"(r[0]), "=r"(r[1]), "=r"(r[2]), "=r"(r[3]) : "r"(addr));
}
__device__ __forceinline__ void mma16816(float* d, const uint32_t* a, uint32_t b0, uint32_t b1) {
    asm volatile(
        "mma.sync.aligned.m16n8k16.row.col.f32.f16.f16.f32 "
        "{%0,%1,%2,%3}, {%4,%5,%6,%7}, {%8,%9}, {%0,%1,%2,%3};"
        : "+f"(d[0]), "+f"(d[1]), "+f"(d[2]), "+f"(d[3])
        : "r"(a[0]), "r"(a[1]), "r"(a[2]), "r"(a[3]), "r"(b0), "r"(b1));
}

__global__ void __launch_bounds__(256, 2) k_gemm_mma(
    const float* __restrict__ A1,
    const __half* __restrict__ W1h, const __half* __restrict__ W1l,
    const float* __restrict__ A2,
    const __half* __restrict__ W2h, const __half* __restrict__ W2l,
    const float* __restrict__ bias, float* __restrict__ C,
    __half* __restrict__ Cb,
    int M, int dual, int relu)
{
    extern __shared__ __align__(16) char smem[];
    uint32_t sb = s2u(smem);
    int tid = threadIdx.x, lane = tid & 31, wid = tid >> 5;
    int bm = blockIdx.x * 128, bn = blockIdx.y * 64;
    int wm = wid & 3, wn = wid >> 2;

    float acc[2][4][4];
    #pragma unroll
    for (int mt = 0; mt < 2; mt++)
        #pragma unroll
        for (int nt = 0; nt < 4; nt++)
            #pragma unroll
            for (int j = 0; j < 4; j++) acc[mt][nt][j] = 0.f;

    int nc = dual ? 16 : 8;
    float4 av[4];
    uint4 bvh, bvl;
    int b_n = tid >> 2, b_c16 = tid & 3;

    auto gload = [&](int c) {
        const float* A = (c >= 8) ? A2 : A1;
        const __half* Bh = (c >= 8) ? W2h : W1h;
        const __half* Bl = (c >= 8) ? W2l : W1l;
        int kk = (c & 7) * 32;
        #pragma unroll
        for (int i = 0; i < 4; i++) {
            int f = tid + i * 256, row = f >> 3, cc = f & 7;
            int grow = bm + row;
            av[i] = (grow < M) ? __ldg((const float4*)(A + (size_t)grow * 256 + kk + cc * 4))
                               : make_float4(0.f, 0.f, 0.f, 0.f);
        }
        size_t boff = (size_t)(bn + b_n) * DF + kk + b_c16 * 8;
        bvh = __ldg((const uint4*)(Bh + boff));
        bvl = __ldg((const uint4*)(Bl + boff));
    };

    auto sstore = [&](int buf) {
        char* st = smem + buf * S_BUF;
        #pragma unroll
        for (int i = 0; i < 4; i++) {
            int f = tid + i * 256, row = f >> 3, cc = f & 7;
            float4 v = av[i];
            uint2 hi = make_uint2(pack_f16(v.x, v.y), pack_f16(v.z, v.w));
            *(uint2*)(st + S_AH + row * 80 + cc * 8) = hi;
        }
        *(uint4*)(st + S_BH + b_n * 80 + b_c16 * 16) = bvh;
        *(uint4*)(st + S_BL + b_n * 80 + b_c16 * 16) = bvl;
    };

    gload(0);
    sstore(0);
    __syncthreads();

    for (int c = 0; c < nc; c++) {
        int buf = c & 1;
        if (c + 1 < nc) gload(c + 1);

        uint32_t base = sb + buf * S_BUF;
        int a_row = wm * 32 + (lane & 15);
        int a_col = (lane >> 4) << 3;
        int b_row0 = wn * 32 + (lane & 7) + ((lane >> 4) << 3);
        int b_col = ((lane >> 3) & 1) << 3;

        #pragma unroll
        for (int ks = 0; ks < 2; ks++) {
            int kh = ks * 16;
            uint32_t ah[8], bh[8], bl[8];
            #pragma unroll
            for (int mt = 0; mt < 2; mt++) {
                uint32_t ad = base + S_AH + (a_row + mt * 16) * 80 + (kh + a_col) * 2;
                ldsm_x4(ah + mt * 4, ad);
            }
            #pragma unroll
            for (int h = 0; h < 2; h++) {
                uint32_t bd = base + S_BH + (b_row0 + h * 16) * 80 + (kh + b_col) * 2;
                ldsm_x4(bh + h * 4, bd);
                ldsm_x4(bl + h * 4, bd + (S_BL - S_BH));
            }
            #pragma unroll
            for (int mt = 0; mt < 2; mt++)
                #pragma unroll
                for (int nt = 0; nt < 4; nt++) {
                    mma16816(acc[mt][nt], ah + mt * 4, bh[nt * 2], bh[nt * 2 + 1]);
                    mma16816(acc[mt][nt], ah + mt * 4, bl[nt * 2], bl[nt * 2 + 1]);
                }
        }
        if (c + 1 < nc) sstore((c + 1) & 1);
        __syncthreads();
    }

    // ---- epilogue: bias + relu, write fp32 C (+ optional fp16 Cb) ----
    int g = lane >> 2, tg = lane & 3;
    #pragma unroll
    for (int mt = 0; mt < 2; mt++) {
        int r0 = bm + wm * 32 + mt * 16 + g;
        #pragma unroll
        for (int nt = 0; nt < 4; nt++) {
            int col = bn + wn * 32 + nt * 8 + tg * 2;
            float bx = __ldg(bias + col), by = __ldg(bias + col + 1);
            float2 v0, v1;
            v0.x = acc[mt][nt][0] + bx; v0.y = acc[mt][nt][1] + by;
            v1.x = acc[mt][nt][2] + bx; v1.y = acc[mt][nt][3] + by;
            if (relu) {
                v0.x = fmaxf(v0.x, 0.f); v0.y = fmaxf(v0.y, 0.f);
                v1.x = fmaxf(v1.x, 0.f); v1.y = fmaxf(v1.y, 0.f);
            }
            if (r0 < M) {
                *(float2*)(C + (size_t)r0 * 256 + col) = v0;
                if (Cb) *(uint32_t*)(Cb + (size_t)r0 * 256 + col) = pack_f16(v0.x, v0.y);
            }
            if (r0 + 8 < M) {
                *(float2*)(C + (size_t)(r0 + 8) * 256 + col) = v1;
                if (Cb) *(uint32_t*)(Cb + (size_t)(r0 + 8) * 256 + col) = pack_f16(v1.x, v1.y);
            }
        }
    }
}

// ---------------- decoder: logits (8) + softmax, warp per node -------------
__global__ void __launch_bounds__(128) k_decoder(
    const float* __restrict__ H, const float* __restrict__ Wm2,
    const float* __restrict__ bm2, float* __restrict__ out)
{
    __shared__ float sW[8 * 256];
    int tid = threadIdx.x;
    #pragma unroll
    for (int i = 0; i < 16; i++) sW[tid + i * 128] = Wm2[tid + i * 128];
    __syncthreads();

    int lane = tid & 31, w = tid >> 5;
    int node = blockIdx.x * 4 + w;
    if (node >= N_NODES) return;

    float acc[8] = {0.f, 0.f, 0.f, 0.f, 0.f, 0.f, 0.f, 0.f};
    #pragma unroll
    for (int j = 0; j < 8; j++) {
        float v = H[(size_t)node * 256 + j * 32 + lane];
        #pragma unroll
        for (int o = 0; o < 8; o++)
            acc[o] = fmaf(v, sW[o * 256 + j * 32 + lane], acc[o]);
    }
    #pragma unroll
    for (int o = 0; o < 8; o++)
        #pragma unroll
        for (int off = 16; off >= 1; off >>= 1)
            acc[o] += __shfl_xor_sync(0xffffffffu, acc[o], off);

    if (lane < 8) {
        float logit = acc[lane] + bm2[lane];
        float m = logit;
        #pragma unroll
        for (int off = 4; off >= 1; off >>= 1)
            m = fmaxf(m, __shfl_xor_sync(0xffu, m, off));
        float ex = expf(logit - m);
        float ssum = ex;
        #pragma unroll
        for (int off = 4; off >= 1; off >>= 1)
            ssum += __shfl_xor_sync(0xffu, ssum, off);
        out[(size_t)node * 8 + lane] = ex / ssum;
    }
}

// ---------------- launch ----------------
extern "C" void kernel_launch(void* const* d_in, const int* in_sizes, int n_in,
                              void* d_out, int out_size) {
    const float* x    = (const float*)d_in[0];
    const void*  edge = d_in[1];
    const float* W1l = (const float*)d_in[2];
    const float* b1  = (const float*)d_in[3];
    const float* W1r = (const float*)d_in[4];
    const float* W2l = (const float*)d_in[5];
    const float* b2  = (const float*)d_in[6];
    const float* W2r = (const float*)d_in[7];
    const float* Wm1 = (const float*)d_in[8];
    const float* bm1 = (const float*)d_in[9];
    const float* Wm2 = (const float*)d_in[10];
    const float* bm2 = (const float*)d_in[11];
    float* out = (float*)d_out;

    float *agg, *h1, *h2;
    __half *wh, *wl, *xb, *h1b;
    cudaGetSymbolAddress((void**)&agg, g_agg);
    cudaGetSymbolAddress((void**)&h1, g_h1);
    cudaGetSymbolAddress((void**)&h2, g_h2);
    cudaGetSymbolAddress((void**)&xb, g_xb);
    cudaGetSymbolAddress((void**)&h1b, g_h1b);
    cudaGetSymbolAddress((void**)&wh, g_wh);
    cudaGetSymbolAddress((void**)&wl, g_wl);

    cudaFuncSetAttribute(k_gemm_mma, cudaFuncAttributeMaxDynamicSharedMemorySize, SMEM_GEMM);

    // weight pre-split + x fp16 copy
    k_wsplit<<<160, 256>>>(W1l, W1r, W2l, W2r, Wm1);
    k_tof16<<<(N_NODES * DF / 8 + 255) / 256, 256>>>(x, xb, N_NODES * DF / 8);

    // CSR build
    k_init<<<(N_NODES + 255) / 256, 256>>>(edge);
    k_count<<<(N_EDGES + 255) / 256, 256>>>(edge);
    k_scanA<<<49, 1024>>>();
    k_scanB<<<1, 64>>>();
    k_scanC<<<49, 1024>>>();
    k_fill<<<(N_EDGES + 255) / 256, 256>>>(edge);

    int aggBlocks = (N_NODES * 32 + 255) / 256;
    dim3 gg((N_NODES + 127) / 128, 4);

    // layer 1: h1 = relu(agg(x)@W1l + x@W1r + b1); also emit h1b (fp16)
    k_aggregate<<<aggBlocks, 256>>>(xb, agg);
    k_gemm_mma<<<gg, 256, SMEM_GEMM>>>(agg, wh + 0 * DF * DF, wl + 0 * DF * DF,
                                       x,   wh + 1 * DF * DF, wl + 1 * DF * DF,
                                       b1, h1, h1b, N_NODES, 1, 1);

    // layer 2: h2 = relu(agg(h1)@W2l + h1@W2r + b2)
    k_aggregate<<<aggBlocks, 256>>>(h1b, agg);
    k_gemm_mma<<<gg, 256, SMEM_GEMM>>>(agg, wh + 2 * DF * DF, wl + 2 * DF * DF,
                                       h1,  wh + 3 * DF * DF, wl + 3 * DF * DF,
                                       b2, h2, nullptr, N_NODES, 1, 1);

    // MLP hidden (reuse h1)
    k_gemm_mma<<<gg, 256, SMEM_GEMM>>>(h2, wh + 4 * DF * DF, wl + 4 * DF * DF,
                                       nullptr, wh + 4 * DF * DF, wl + 4 * DF * DF,
                                       bm1, h1, nullptr, N_NODES, 0, 1);

    // decoder + softmax
    k_decoder<<<(N_NODES + 3) / 4, 128>>>(h1, Wm2, bm2, out);
}

// round 12
// speedup vs baseline: 1.5937x; 1.2917x over previous
#include <cuda_runtime.h>
#include <cuda_fp16.h>
#include <cstdint>

#define N_NODES 50000
#define N_EDGES 800000
#define DF 256

// ---------------- device scratch ----------------
__device__ int    g_is64;
__device__ int    g_deg[N_NODES];
__device__ int    g_cursor[N_NODES];
__device__ int    g_rowstart[N_NODES + 1];
__device__ int    g_blocksum[64];
__device__ int    g_blockoff[64];
__device__ int    g_nbr[N_EDGES];
__device__ __half g_xb[(size_t)N_NODES * DF];
__device__ __half g_aggh[(size_t)N_NODES * DF];
__device__ __half g_h1b[(size_t)N_NODES * DF];
__device__ __half g_h2b[(size_t)N_NODES * DF];
__device__ float  g_hm[(size_t)N_NODES * DF];
__device__ __half g_w[5][DF * DF];

__device__ __forceinline__ int edge_at(const void* edge, int idx) {
    if (g_is64) return (int)((const long long*)edge)[idx];
    return ((const int*)edge)[idx];
}

// ---------------- helpers ----------------
__device__ __forceinline__ uint32_t s2u(const void* p) {
    uint32_t a;
    asm("{ .reg .u64 t; cvta.to.shared.u64 t, %1; cvt.u32.u64 %0, t; }" : "=r"(a) : "l"(p));
    return a;
}
__device__ __forceinline__ uint32_t pack_f16(float a, float b) {
    __half2 h = __floats2half2_rn(a, b);
    return *reinterpret_cast<uint32_t*>(&h);
}

// ---------------- fp32 -> fp16 row copy ----------------
__global__ void k_tof16(const float* __restrict__ X, __half* __restrict__ Xb, int n8) {
    int i = blockIdx.x * blockDim.x + threadIdx.x;
    if (i >= n8) return;
    const float4* p = (const float4*)X + (size_t)i * 2;
    float4 v0 = __ldg(p), v1 = __ldg(p + 1);
    uint4 o;
    o.x = pack_f16(v0.x, v0.y); o.y = pack_f16(v0.z, v0.w);
    o.z = pack_f16(v1.x, v1.y); o.w = pack_f16(v1.z, v1.w);
    ((uint4*)Xb)[i] = o;
}

// ---------------- weight fp16 convert: 5 matrices, one launch ----------------
__global__ void k_wconv(const float* __restrict__ w0, const float* __restrict__ w1,
                        const float* __restrict__ w2, const float* __restrict__ w3,
                        const float* __restrict__ w4) {
    int m = blockIdx.x >> 5;
    int i = (blockIdx.x & 31) * blockDim.x + threadIdx.x;
    const float* W = (m == 0) ? w0 : (m == 1) ? w1 : (m == 2) ? w2 : (m == 3) ? w3 : w4;
    const float4* p = (const float4*)W + (size_t)i * 2;
    float4 v0 = __ldg(p), v1 = __ldg(p + 1);
    uint4 o;
    o.x = pack_f16(v0.x, v0.y); o.y = pack_f16(v0.z, v0.w);
    o.z = pack_f16(v1.x, v1.y); o.w = pack_f16(v1.z, v1.w);
    ((uint4*)g_w[m])[i] = o;
}

// ---------------- CSR build ----------------
__global__ void k_init(const void* edge) {
    int i = blockIdx.x * blockDim.x + threadIdx.x;
    if (i < N_NODES) { g_deg[i] = 0; g_cursor[i] = 0; }
    if (blockIdx.x == 0 && threadIdx.x == 0) {
        const long long* e = (const long long*)edge;
        int ok = 1;
        for (int j = 0; j < 16; j++) {
            long long v = e[j];
            if (v < 0 || v >= (long long)N_NODES) ok = 0;
        }
        g_is64 = ok;
    }
}

__global__ void k_count(const void* __restrict__ edge) {
    int e = blockIdx.x * blockDim.x + threadIdx.x;
    if (e >= N_EDGES) return;
    int dst = edge_at(edge, N_EDGES + e);
    atomicAdd(&g_deg[dst], 1);
}

__global__ void k_scanA() {
    __shared__ int ws[32];
    int b = blockIdx.x, t = threadIdx.x, lane = t & 31, w = t >> 5;
    int i = b * 1024 + t;
    int v = (i < N_NODES) ? g_deg[i] : 0;
    int sv = v;
    #pragma unroll
    for (int off = 1; off < 32; off <<= 1) {
        int x = __shfl_up_sync(0xffffffffu, sv, off);
        if (lane >= off) sv += x;
    }
    if (lane == 31) ws[w] = sv;
    __syncthreads();
    if (w == 0) {
        int s = ws[lane];
        #pragma unroll
        for (int off = 1; off < 32; off <<= 1) {
            int x = __shfl_up_sync(0xffffffffu, s, off);
            if (lane >= off) s += x;
        }
        ws[lane] = s;
    }
    __syncthreads();
    int tot = sv + ((w > 0) ? ws[w - 1] : 0);
    if (i < N_NODES) g_rowstart[i + 1] = tot;
    if (t == 1023) g_blocksum[b] = tot;
    if (b == 0 && t == 0) g_rowstart[0] = 0;
}

__global__ void k_scanB() {
    __shared__ int s[64];
    int t = threadIdx.x;
    s[t] = (t < 49) ? g_blocksum[t] : 0;
    __syncthreads();
    if (t == 0) {
        int acc = 0;
        for (int j = 0; j < 49; j++) { int x = s[j]; s[j] = acc; acc += x; }
    }
    __syncthreads();
    if (t < 49) g_blockoff[t] = s[t];
}

__global__ void k_scanC() {
    int b = blockIdx.x, t = threadIdx.x;
    int i = b * 1024 + t;
    if (i < N_NODES) g_rowstart[i + 1] += g_blockoff[b];
}

__global__ void k_fill(const void* __restrict__ edge) {
    int e = blockIdx.x * blockDim.x + threadIdx.x;
    if (e >= N_EDGES) return;
    int src = edge_at(edge, e);
    int dst = edge_at(edge, N_EDGES + e);
    int p = atomicAdd(&g_cursor[dst], 1);
    g_nbr[g_rowstart[dst] + p] = src;
}

// ---------------- mean aggregation: warp per node, fp16 in/out, fp32 acc ----------------
__global__ void k_aggregate(const __half* __restrict__ Xb, __half* __restrict__ Oh) {
    int gw = (blockIdx.x * blockDim.x + threadIdx.x) >> 5;
    int lane = threadIdx.x & 31;
    if (gw >= N_NODES) return;
    int s = g_rowstart[gw], e = g_rowstart[gw + 1];
    float acc[8] = {0.f, 0.f, 0.f, 0.f, 0.f, 0.f, 0.f, 0.f};
    int j = s;
    for (; j + 2 <= e; j += 2) {
        int s0 = g_nbr[j], s1 = g_nbr[j + 1];
        uint4 u = __ldg((const uint4*)(Xb + (size_t)s0 * DF) + lane);
        uint4 w = __ldg((const uint4*)(Xb + (size_t)s1 * DF) + lane);
        const __half2* up = (const __half2*)&u;
        const __half2* wp = (const __half2*)&w;
        #pragma unroll
        for (int i = 0; i < 4; i++) {
            float2 a = __half22float2(up[i]);
            float2 b = __half22float2(wp[i]);
            acc[2 * i]     += a.x + b.x;
            acc[2 * i + 1] += a.y + b.y;
        }
    }
    if (j < e) {
        int s0 = g_nbr[j];
        uint4 u = __ldg((const uint4*)(Xb + (size_t)s0 * DF) + lane);
        const __half2* up = (const __half2*)&u;
        #pragma unroll
        for (int i = 0; i < 4; i++) {
            float2 a = __half22float2(up[i]);
            acc[2 * i]     += a.x;
            acc[2 * i + 1] += a.y;
        }
    }
    int cnt = e - s;
    float inv = 1.0f / (float)(cnt > 1 ? cnt : 1);
    uint4 o;
    o.x = pack_f16(acc[0] * inv, acc[1] * inv);
    o.y = pack_f16(acc[2] * inv, acc[3] * inv);
    o.z = pack_f16(acc[4] * inv, acc[5] * inv);
    o.w = pack_f16(acc[6] * inv, acc[7] * inv);
    ((uint4*)(Oh + (size_t)gw * DF))[lane] = o;
}

// ======================= pure fp16 mma.sync GEMM =======================
// C = relu?( A1 @ W1^T [+ A2 @ W2^T] + bias ). All operands fp16, fp32 acc.
// CTA 128(M) x 64(N), chunk K=32, double-buffered smem, 2 CTAs/SM.  [R6 structure]

#define S_A 0
#define S_B 10240
#define S_BUF 15360
#define SMEM_GEMM (2 * S_BUF)

__device__ __forceinline__ void ldsm_x4(uint32_t* r, uint32_t addr) {
    asm volatile("ldmatrix.sync.aligned.m8n8.x4.shared.b16 {%0,%1,%2,%3}, [%4];"
                 : "=r"(r[0]), "=r"(r[1]), "=r"(r[2]), "=r"(r[3]) : "r"(addr));
}
__device__ __forceinline__ void mma16816(float* d, const uint32_t* a, uint32_t b0, uint32_t b1) {
    asm volatile(
        "mma.sync.aligned.m16n8k16.row.col.f32.f16.f16.f32 "
        "{%0,%1,%2,%3}, {%4,%5,%6,%7}, {%8,%9}, {%0,%1,%2,%3};"
        : "+f"(d[0]), "+f"(d[1]), "+f"(d[2]), "+f"(d[3])
        : "r"(a[0]), "r"(a[1]), "r"(a[2]), "r"(a[3]), "r"(b0), "r"(b1));
}

__global__ void __launch_bounds__(256, 2) k_gemm_mma(
    const __half* __restrict__ A1, const __half* __restrict__ W1,
    const __half* __restrict__ A2, const __half* __restrict__ W2,
    const float* __restrict__ bias,
    __half* __restrict__ Ch, float* __restrict__ Cf,
    int M, int dual, int relu)
{
    extern __shared__ __align__(16) char smem[];
    uint32_t sb = s2u(smem);
    int tid = threadIdx.x, lane = tid & 31, wid = tid >> 5;
    int bm = blockIdx.x * 128, bn = blockIdx.y * 64;
    int wm = wid & 3, wn = wid >> 2;

    float acc[2][4][4];
    #pragma unroll
    for (int mt = 0; mt < 2; mt++)
        #pragma unroll
        for (int nt = 0; nt < 4; nt++)
            #pragma unroll
            for (int j = 0; j < 4; j++) acc[mt][nt][j] = 0.f;

    int nc = dual ? 16 : 8;
    uint4 av[2], bv;
    int b_n = tid >> 2, b_q = tid & 3;

    auto gload = [&](int c) {
        const __half* A = (c >= 8) ? A2 : A1;
        const __half* B = (c >= 8) ? W2 : W1;
        int kk = (c & 7) * 32;
        #pragma unroll
        for (int i = 0; i < 2; i++) {
            int f = tid + i * 256, row = f >> 2, q = f & 3;
            int grow = bm + row;
            av[i] = (grow < M) ? __ldg((const uint4*)(A + (size_t)grow * DF + kk) + q)
                               : make_uint4(0u, 0u, 0u, 0u);
        }
        bv = __ldg((const uint4*)(B + (size_t)(bn + b_n) * DF + kk) + b_q);
    };

    auto sstore = [&](int buf) {
        char* st = smem + buf * S_BUF;
        #pragma unroll
        for (int i = 0; i < 2; i++) {
            int f = tid + i * 256, row = f >> 2, q = f & 3;
            *(uint4*)(st + S_A + row * 80 + q * 16) = av[i];
        }
        *(uint4*)(st + S_B + b_n * 80 + b_q * 16) = bv;
    };

    gload(0);
    sstore(0);
    __syncthreads();

    for (int c = 0; c < nc; c++) {
        int buf = c & 1;
        if (c + 1 < nc) gload(c + 1);

        uint32_t base = sb + buf * S_BUF;
        int a_row = wm * 32 + (lane & 15);
        int a_col = (lane >> 4) << 3;
        int b_row0 = wn * 32 + (lane & 7) + ((lane >> 4) << 3);
        int b_col = ((lane >> 3) & 1) << 3;

        #pragma unroll
        for (int ks = 0; ks < 2; ks++) {
            int kh = ks * 16;
            uint32_t ah[8], bh[8];
            #pragma unroll
            for (int mt = 0; mt < 2; mt++) {
                uint32_t ad = base + S_A + (a_row + mt * 16) * 80 + (kh + a_col) * 2;
                ldsm_x4(ah + mt * 4, ad);
            }
            #pragma unroll
            for (int h = 0; h < 2; h++) {
                uint32_t bd = base + S_B + (b_row0 + h * 16) * 80 + (kh + b_col) * 2;
                ldsm_x4(bh + h * 4, bd);
            }
            #pragma unroll
            for (int mt = 0; mt < 2; mt++)
                #pragma unroll
                for (int nt = 0; nt < 4; nt++)
                    mma16816(acc[mt][nt], ah + mt * 4, bh[nt * 2], bh[nt * 2 + 1]);
        }
        if (c + 1 < nc) sstore((c + 1) & 1);
        __syncthreads();
    }

    // ---- epilogue: bias + relu; write fp16 Ch and/or fp32 Cf ----
    int g = lane >> 2, tg = lane & 3;
    #pragma unroll
    for (int mt = 0; mt < 2; mt++) {
        int r0 = bm + wm * 32 + mt * 16 + g;
        #pragma unroll
        for (int nt = 0; nt < 4; nt++) {
            int col = bn + wn * 32 + nt * 8 + tg * 2;
            float bx = __ldg(bias + col), by = __ldg(bias + col + 1);
            float2 v0, v1;
            v0.x = acc[mt][nt][0] + bx; v0.y = acc[mt][nt][1] + by;
            v1.x = acc[mt][nt][2] + bx; v1.y = acc[mt][nt][3] + by;
            if (relu) {
                v0.x = fmaxf(v0.x, 0.f); v0.y = fmaxf(v0.y, 0.f);
                v1.x = fmaxf(v1.x, 0.f); v1.y = fmaxf(v1.y, 0.f);
            }
            if (r0 < M) {
                if (Ch) *(uint32_t*)(Ch + (size_t)r0 * DF + col) = pack_f16(v0.x, v0.y);
                if (Cf) *(float2*)(Cf + (size_t)r0 * DF + col) = v0;
            }
            if (r0 + 8 < M) {
                if (Ch) *(uint32_t*)(Ch + (size_t)(r0 + 8) * DF + col) = pack_f16(v1.x, v1.y);
                if (Cf) *(float2*)(Cf + (size_t)(r0 + 8) * DF + col) = v1;
            }
        }
    }
}

// ---------------- decoder: logits (8) + softmax, warp per node -------------
__global__ void __launch_bounds__(128) k_decoder(
    const float* __restrict__ H, const float* __restrict__ Wm2,
    const float* __restrict__ bm2, float* __restrict__ out)
{
    __shared__ float sW[8 * 256];
    int tid = threadIdx.x;
    #pragma unroll
    for (int i = 0; i < 16; i++) sW[tid + i * 128] = Wm2[tid + i * 128];
    __syncthreads();

    int lane = tid & 31, w = tid >> 5;
    int node = blockIdx.x * 4 + w;
    if (node >= N_NODES) return;

    float acc[8] = {0.f, 0.f, 0.f, 0.f, 0.f, 0.f, 0.f, 0.f};
    #pragma unroll
    for (int j = 0; j < 8; j++) {
        float v = H[(size_t)node * 256 + j * 32 + lane];
        #pragma unroll
        for (int o = 0; o < 8; o++)
            acc[o] = fmaf(v, sW[o * 256 + j * 32 + lane], acc[o]);
    }
    #pragma unroll
    for (int o = 0; o < 8; o++)
        #pragma unroll
        for (int off = 16; off >= 1; off >>= 1)
            acc[o] += __shfl_xor_sync(0xffffffffu, acc[o], off);

    if (lane < 8) {
        float logit = acc[lane] + bm2[lane];
        float m = logit;
        #pragma unroll
        for (int off = 4; off >= 1; off >>= 1)
            m = fmaxf(m, __shfl_xor_sync(0xffu, m, off));
        float ex = expf(logit - m);
        float ssum = ex;
        #pragma unroll
        for (int off = 4; off >= 1; off >>= 1)
            ssum += __shfl_xor_sync(0xffu, ssum, off);
        out[(size_t)node * 8 + lane] = ex / ssum;
    }
}

// ---------------- launch ----------------
extern "C" void kernel_launch(void* const* d_in, const int* in_sizes, int n_in,
                              void* d_out, int out_size) {
    const float* x    = (const float*)d_in[0];
    const void*  edge = d_in[1];
    const float* W1l = (const float*)d_in[2];
    const float* b1  = (const float*)d_in[3];
    const float* W1r = (const float*)d_in[4];
    const float* W2l = (const float*)d_in[5];
    const float* b2  = (const float*)d_in[6];
    const float* W2r = (const float*)d_in[7];
    const float* Wm1 = (const float*)d_in[8];
    const float* bm1 = (const float*)d_in[9];
    const float* Wm2 = (const float*)d_in[10];
    const float* bm2 = (const float*)d_in[11];
    float* out = (float*)d_out;

    __half *xb, *aggh, *h1b, *h2b, *w;
    float *hm;
    cudaGetSymbolAddress((void**)&xb, g_xb);
    cudaGetSymbolAddress((void**)&aggh, g_aggh);
    cudaGetSymbolAddress((void**)&h1b, g_h1b);
    cudaGetSymbolAddress((void**)&h2b, g_h2b);
    cudaGetSymbolAddress((void**)&hm, g_hm);
    cudaGetSymbolAddress((void**)&w, g_w);

    cudaFuncSetAttribute(k_gemm_mma, cudaFuncAttributeMaxDynamicSharedMemorySize, SMEM_GEMM);

    // weight fp16 convert + x fp16 copy
    k_wconv<<<160, 256>>>(W1l, W1r, W2l, W2r, Wm1);
    k_tof16<<<(N_NODES * DF / 8 + 255) / 256, 256>>>(x, xb, N_NODES * DF / 8);

    // CSR build
    k_init<<<(N_NODES + 255) / 256, 256>>>(edge);
    k_count<<<(N_EDGES + 255) / 256, 256>>>(edge);
    k_scanA<<<49, 1024>>>();
    k_scanB<<<1, 64>>>();
    k_scanC<<<49, 1024>>>();
    k_fill<<<(N_EDGES + 255) / 256, 256>>>(edge);

    int aggBlocks = (N_NODES * 32 + 255) / 256;
    dim3 gg((N_NODES + 127) / 128, 4);

    // layer 1: h1 = relu(agg(x)@W1l + x@W1r + b1)  (fp16 out)
    k_aggregate<<<aggBlocks, 256>>>(xb, aggh);
    k_gemm_mma<<<gg, 256, SMEM_GEMM>>>(aggh, w + 0 * DF * DF, xb, w + 1 * DF * DF,
                                       b1, h1b, nullptr, N_NODES, 1, 1);

    // layer 2: h2 = relu(agg(h1)@W2l + h1@W2r + b2)  (fp16 out)
    k_aggregate<<<aggBlocks, 256>>>(h1b, aggh);
    k_gemm_mma<<<gg, 256, SMEM_GEMM>>>(aggh, w + 2 * DF * DF, h1b, w + 3 * DF * DF,
                                       b2, h2b, nullptr, N_NODES, 1, 1);

    // MLP hidden: hm = relu(h2@Wm1 + bm1)  (fp32 out for decoder)
    k_gemm_mma<<<gg, 256, SMEM_GEMM>>>(h2b, w + 4 * DF * DF, nullptr, w + 4 * DF * DF,
                                       bm1, nullptr, hm, N_NODES, 0, 1);

    // decoder + softmax
    k_decoder<<<(N_NODES + 3) / 4, 128>>>(hm, Wm2, bm2, out);
}

// round 13
// speedup vs baseline: 1.6457x; 1.0326x over previous
#include <cuda_runtime.h>
#include <cuda_fp16.h>
#include <cstdint>

#define N_NODES 50000
#define N_EDGES 800000
#define DF 256

// ---------------- device scratch ----------------
__device__ int    g_is64;
__device__ int    g_deg[N_NODES];
__device__ int    g_cursor[N_NODES];
__device__ int    g_rowstart[N_NODES + 1];
__device__ int    g_blocksum[64];
__device__ int    g_blockoff[64];
__device__ int    g_nbr[N_EDGES];
__device__ __half g_xb[(size_t)N_NODES * DF];
__device__ __half g_aggh[(size_t)N_NODES * DF];
__device__ __half g_h1b[(size_t)N_NODES * DF];
__device__ __half g_h2b[(size_t)N_NODES * DF];
__device__ __half g_hm[(size_t)N_NODES * DF];
__device__ __half g_w[5][DF * DF];

__device__ __forceinline__ int edge_at(const void* edge, int idx) {
    if (g_is64) return (int)((const long long*)edge)[idx];
    return ((const int*)edge)[idx];
}

// ---------------- helpers ----------------
__device__ __forceinline__ uint32_t s2u(const void* p) {
    uint32_t a;
    asm("{ .reg .u64 t; cvta.to.shared.u64 t, %1; cvt.u32.u64 %0, t; }" : "=r"(a) : "l"(p));
    return a;
}
__device__ __forceinline__ uint32_t pack_f16(float a, float b) {
    __half2 h = __floats2half2_rn(a, b);
    return *reinterpret_cast<uint32_t*>(&h);
}

// ---------------- fused converts: weights (fp16) + x (fp16), one launch ----------------
// blocks [0,160): 5 weight matrices (32 blocks each). blocks [160, 160+6250): x rows.
__global__ void k_convert(const float* __restrict__ w0, const float* __restrict__ w1,
                          const float* __restrict__ w2, const float* __restrict__ w3,
                          const float* __restrict__ w4, const float* __restrict__ x) {
    int b = blockIdx.x;
    const float* src;
    uint4* dst;
    int i;
    if (b < 160) {
        int m = b >> 5;
        i = (b & 31) * blockDim.x + threadIdx.x;
        src = (m == 0) ? w0 : (m == 1) ? w1 : (m == 2) ? w2 : (m == 3) ? w3 : w4;
        dst = (uint4*)g_w[m];
    } else {
        i = (b - 160) * blockDim.x + threadIdx.x;
        if (i >= N_NODES * DF / 8) return;
        src = x;
        dst = (uint4*)g_xb;
    }
    const float4* p = (const float4*)src + (size_t)i * 2;
    float4 v0 = __ldg(p), v1 = __ldg(p + 1);
    uint4 o;
    o.x = pack_f16(v0.x, v0.y); o.y = pack_f16(v0.z, v0.w);
    o.z = pack_f16(v1.x, v1.y); o.w = pack_f16(v1.z, v1.w);
    dst[i] = o;
}

// ---------------- CSR build ----------------
__global__ void k_init(const void* edge) {
    int i = blockIdx.x * blockDim.x + threadIdx.x;
    if (i < N_NODES) { g_deg[i] = 0; g_cursor[i] = 0; }
    if (blockIdx.x == 0 && threadIdx.x == 0) {
        const long long* e = (const long long*)edge;
        int ok = 1;
        for (int j = 0; j < 16; j++) {
            long long v = e[j];
            if (v < 0 || v >= (long long)N_NODES) ok = 0;
        }
        g_is64 = ok;
    }
}

__global__ void k_count(const void* __restrict__ edge) {
    int e = blockIdx.x * blockDim.x + threadIdx.x;
    if (e >= N_EDGES) return;
    int dst = edge_at(edge, N_EDGES + e);
    atomicAdd(&g_deg[dst], 1);
}

__global__ void k_scanA() {
    __shared__ int ws[32];
    int b = blockIdx.x, t = threadIdx.x, lane = t & 31, w = t >> 5;
    int i = b * 1024 + t;
    int v = (i < N_NODES) ? g_deg[i] : 0;
    int sv = v;
    #pragma unroll
    for (int off = 1; off < 32; off <<= 1) {
        int x = __shfl_up_sync(0xffffffffu, sv, off);
        if (lane >= off) sv += x;
    }
    if (lane == 31) ws[w] = sv;
    __syncthreads();
    if (w == 0) {
        int s = ws[lane];
        #pragma unroll
        for (int off = 1; off < 32; off <<= 1) {
            int x = __shfl_up_sync(0xffffffffu, s, off);
            if (lane >= off) s += x;
        }
        ws[lane] = s;
    }
    __syncthreads();
    int tot = sv + ((w > 0) ? ws[w - 1] : 0);
    if (i < N_NODES) g_rowstart[i + 1] = tot;
    if (t == 1023) g_blocksum[b] = tot;
    if (b == 0 && t == 0) g_rowstart[0] = 0;
}

__global__ void k_scanB() {
    __shared__ int s[64];
    int t = threadIdx.x;
    s[t] = (t < 49) ? g_blocksum[t] : 0;
    __syncthreads();
    if (t == 0) {
        int acc = 0;
        for (int j = 0; j < 49; j++) { int x = s[j]; s[j] = acc; acc += x; }
    }
    __syncthreads();
    if (t < 49) g_blockoff[t] = s[t];
}

__global__ void k_scanC() {
    int b = blockIdx.x, t = threadIdx.x;
    int i = b * 1024 + t;
    if (i < N_NODES) g_rowstart[i + 1] += g_blockoff[b];
}

__global__ void k_fill(const void* __restrict__ edge) {
    int e = blockIdx.x * blockDim.x + threadIdx.x;
    if (e >= N_EDGES) return;
    int src = edge_at(edge, e);
    int dst = edge_at(edge, N_EDGES + e);
    int p = atomicAdd(&g_cursor[dst], 1);
    g_nbr[g_rowstart[dst] + p] = src;
}

// ---------------- mean aggregation: warp per node, fp16, 4-edge unroll ----------------
__global__ void k_aggregate(const __half* __restrict__ Xb, __half* __restrict__ Oh) {
    int gw = (blockIdx.x * blockDim.x + threadIdx.x) >> 5;
    int lane = threadIdx.x & 31;
    if (gw >= N_NODES) return;
    int s = g_rowstart[gw], e = g_rowstart[gw + 1];
    float acc[8] = {0.f, 0.f, 0.f, 0.f, 0.f, 0.f, 0.f, 0.f};
    int j = s;
    for (; j + 4 <= e; j += 4) {
        int s0 = g_nbr[j], s1 = g_nbr[j + 1], s2 = g_nbr[j + 2], s3 = g_nbr[j + 3];
        uint4 u0 = __ldg((const uint4*)(Xb + (size_t)s0 * DF) + lane);
        uint4 u1 = __ldg((const uint4*)(Xb + (size_t)s1 * DF) + lane);
        uint4 u2 = __ldg((const uint4*)(Xb + (size_t)s2 * DF) + lane);
        uint4 u3 = __ldg((const uint4*)(Xb + (size_t)s3 * DF) + lane);
        const __half2* p0 = (const __half2*)&u0;
        const __half2* p1 = (const __half2*)&u1;
        const __half2* p2 = (const __half2*)&u2;
        const __half2* p3 = (const __half2*)&u3;
        #pragma unroll
        for (int i = 0; i < 4; i++) {
            float2 a = __half22float2(p0[i]);
            float2 b = __half22float2(p1[i]);
            float2 c = __half22float2(p2[i]);
            float2 d = __half22float2(p3[i]);
            acc[2 * i]     += (a.x + b.x) + (c.x + d.x);
            acc[2 * i + 1] += (a.y + b.y) + (c.y + d.y);
        }
    }
    for (; j < e; j++) {
        int s0 = g_nbr[j];
        uint4 u = __ldg((const uint4*)(Xb + (size_t)s0 * DF) + lane);
        const __half2* up = (const __half2*)&u;
        #pragma unroll
        for (int i = 0; i < 4; i++) {
            float2 a = __half22float2(up[i]);
            acc[2 * i]     += a.x;
            acc[2 * i + 1] += a.y;
        }
    }
    int cnt = e - s;
    float inv = 1.0f / (float)(cnt > 1 ? cnt : 1);
    uint4 o;
    o.x = pack_f16(acc[0] * inv, acc[1] * inv);
    o.y = pack_f16(acc[2] * inv, acc[3] * inv);
    o.z = pack_f16(acc[4] * inv, acc[5] * inv);
    o.w = pack_f16(acc[6] * inv, acc[7] * inv);
    ((uint4*)(Oh + (size_t)gw * DF))[lane] = o;
}

// ======================= pure fp16 mma.sync GEMM =======================
// C = relu?( A1 @ W1^T [+ A2 @ W2^T] + bias ). All operands fp16, fp32 acc.
// CTA 128(M) x 64(N), chunk K=32, double-buffered smem, 2 CTAs/SM.  [R6 structure]

#define S_A 0
#define S_B 10240
#define S_BUF 15360
#define SMEM_GEMM (2 * S_BUF)

__device__ __forceinline__ void ldsm_x4(uint32_t* r, uint32_t addr) {
    asm volatile("ldmatrix.sync.aligned.m8n8.x4.shared.b16 {%0,%1,%2,%3}, [%4];"
                 : "=r"(r[0]), "=r"(r[1]), "=r"(r[2]), "=r"(r[3]) : "r"(addr));
}
__device__ __forceinline__ void mma16816(float* d, const uint32_t* a, uint32_t b0, uint32_t b1) {
    asm volatile(
        "mma.sync.aligned.m16n8k16.row.col.f32.f16.f16.f32 "
        "{%0,%1,%2,%3}, {%4,%5,%6,%7}, {%8,%9}, {%0,%1,%2,%3};"
        : "+f"(d[0]), "+f"(d[1]), "+f"(d[2]), "+f"(d[3])
        : "r"(a[0]), "r"(a[1]), "r"(a[2]), "r"(a[3]), "r"(b0), "r"(b1));
}

__global__ void __launch_bounds__(256, 2) k_gemm_mma(
    const __half* __restrict__ A1, const __half* __restrict__ W1,
    const __half* __restrict__ A2, const __half* __restrict__ W2,
    const float* __restrict__ bias,
    __half* __restrict__ Ch,
    int M, int dual, int relu)
{
    extern __shared__ __align__(16) char smem[];
    uint32_t sb = s2u(smem);
    int tid = threadIdx.x, lane = tid & 31, wid = tid >> 5;
    int bm = blockIdx.x * 128, bn = blockIdx.y * 64;
    int wm = wid & 3, wn = wid >> 2;

    float acc[2][4][4];
    #pragma unroll
    for (int mt = 0; mt < 2; mt++)
        #pragma unroll
        for (int nt = 0; nt < 4; nt++)
            #pragma unroll
            for (int j = 0; j < 4; j++) acc[mt][nt][j] = 0.f;

    int nc = dual ? 16 : 8;
    uint4 av[2], bv;
    int b_n = tid >> 2, b_q = tid & 3;

    auto gload = [&](int c) {
        const __half* A = (c >= 8) ? A2 : A1;
        const __half* B = (c >= 8) ? W2 : W1;
        int kk = (c & 7) * 32;
        #pragma unroll
        for (int i = 0; i < 2; i++) {
            int f = tid + i * 256, row = f >> 2, q = f & 3;
            int grow = bm + row;
            av[i] = (grow < M) ? __ldg((const uint4*)(A + (size_t)grow * DF + kk) + q)
                               : make_uint4(0u, 0u, 0u, 0u);
        }
        bv = __ldg((const uint4*)(B + (size_t)(bn + b_n) * DF + kk) + b_q);
    };

    auto sstore = [&](int buf) {
        char* st = smem + buf * S_BUF;
        #pragma unroll
        for (int i = 0; i < 2; i++) {
            int f = tid + i * 256, row = f >> 2, q = f & 3;
            *(uint4*)(st + S_A + row * 80 + q * 16) = av[i];
        }
        *(uint4*)(st + S_B + b_n * 80 + b_q * 16) = bv;
    };

    gload(0);
    sstore(0);
    __syncthreads();

    for (int c = 0; c < nc; c++) {
        int buf = c & 1;
        if (c + 1 < nc) gload(c + 1);

        uint32_t base = sb + buf * S_BUF;
        int a_row = wm * 32 + (lane & 15);
        int a_col = (lane >> 4) << 3;
        int b_row0 = wn * 32 + (lane & 7) + ((lane >> 4) << 3);
        int b_col = ((lane >> 3) & 1) << 3;

        #pragma unroll
        for (int ks = 0; ks < 2; ks++) {
            int kh = ks * 16;
            uint32_t ah[8], bh[8];
            #pragma unroll
            for (int mt = 0; mt < 2; mt++) {
                uint32_t ad = base + S_A + (a_row + mt * 16) * 80 + (kh + a_col) * 2;
                ldsm_x4(ah + mt * 4, ad);
            }
            #pragma unroll
            for (int h = 0; h < 2; h++) {
                uint32_t bd = base + S_B + (b_row0 + h * 16) * 80 + (kh + b_col) * 2;
                ldsm_x4(bh + h * 4, bd);
            }
            #pragma unroll
            for (int mt = 0; mt < 2; mt++)
                #pragma unroll
                for (int nt = 0; nt < 4; nt++)
                    mma16816(acc[mt][nt], ah + mt * 4, bh[nt * 2], bh[nt * 2 + 1]);
        }
        if (c + 1 < nc) sstore((c + 1) & 1);
        __syncthreads();
    }

    // ---- epilogue: bias + relu; write fp16 ----
    int g = lane >> 2, tg = lane & 3;
    #pragma unroll
    for (int mt = 0; mt < 2; mt++) {
        int r0 = bm + wm * 32 + mt * 16 + g;
        #pragma unroll
        for (int nt = 0; nt < 4; nt++) {
            int col = bn + wn * 32 + nt * 8 + tg * 2;
            float bx = __ldg(bias + col), by = __ldg(bias + col + 1);
            float2 v0, v1;
            v0.x = acc[mt][nt][0] + bx; v0.y = acc[mt][nt][1] + by;
            v1.x = acc[mt][nt][2] + bx; v1.y = acc[mt][nt][3] + by;
            if (relu) {
                v0.x = fmaxf(v0.x, 0.f); v0.y = fmaxf(v0.y, 0.f);
                v1.x = fmaxf(v1.x, 0.f); v1.y = fmaxf(v1.y, 0.f);
            }
            if (r0 < M)
                *(uint32_t*)(Ch + (size_t)r0 * DF + col) = pack_f16(v0.x, v0.y);
            if (r0 + 8 < M)
                *(uint32_t*)(Ch + (size_t)(r0 + 8) * DF + col) = pack_f16(v1.x, v1.y);
        }
    }
}

// ---------------- decoder: logits (8) + softmax, warp per node (fp16 input) -----
__global__ void __launch_bounds__(128) k_decoder(
    const __half* __restrict__ H, const float* __restrict__ Wm2,
    const float* __restrict__ bm2, float* __restrict__ out)
{
    __shared__ float sW[8 * 256];
    int tid = threadIdx.x;
    #pragma unroll
    for (int i = 0; i < 16; i++) sW[tid + i * 128] = Wm2[tid + i * 128];
    __syncthreads();

    int lane = tid & 31, w = tid >> 5;
    int node = blockIdx.x * 4 + w;
    if (node >= N_NODES) return;

    float acc[8] = {0.f, 0.f, 0.f, 0.f, 0.f, 0.f, 0.f, 0.f};
    #pragma unroll
    for (int j = 0; j < 4; j++) {
        __half2 h2v = *(const __half2*)(H + (size_t)node * DF + j * 64 + lane * 2);
        float2 v = __half22float2(h2v);
        #pragma unroll
        for (int o = 0; o < 8; o++) {
            acc[o] = fmaf(v.x, sW[o * 256 + j * 64 + lane * 2], acc[o]);
            acc[o] = fmaf(v.y, sW[o * 256 + j * 64 + lane * 2 + 1], acc[o]);
        }
    }
    #pragma unroll
    for (int o = 0; o < 8; o++)
        #pragma unroll
        for (int off = 16; off >= 1; off >>= 1)
            acc[o] += __shfl_xor_sync(0xffffffffu, acc[o], off);

    if (lane < 8) {
        float logit = acc[lane] + bm2[lane];
        float m = logit;
        #pragma unroll
        for (int off = 4; off >= 1; off >>= 1)
            m = fmaxf(m, __shfl_xor_sync(0xffu, m, off));
        float ex = expf(logit - m);
        float ssum = ex;
        #pragma unroll
        for (int off = 4; off >= 1; off >>= 1)
            ssum += __shfl_xor_sync(0xffu, ssum, off);
        out[(size_t)node * 8 + lane] = ex / ssum;
    }
}

// ---------------- launch ----------------
extern "C" void kernel_launch(void* const* d_in, const int* in_sizes, int n_in,
                              void* d_out, int out_size) {
    const float* x    = (const float*)d_in[0];
    const void*  edge = d_in[1];
    const float* W1l = (const float*)d_in[2];
    const float* b1  = (const float*)d_in[3];
    const float* W1r = (const float*)d_in[4];
    const float* W2l = (const float*)d_in[5];
    const float* b2  = (const float*)d_in[6];
    const float* W2r = (const float*)d_in[7];
    const float* Wm1 = (const float*)d_in[8];
    const float* bm1 = (const float*)d_in[9];
    const float* Wm2 = (const float*)d_in[10];
    const float* bm2 = (const float*)d_in[11];
    float* out = (float*)d_out;

    __half *xb, *aggh, *h1b, *h2b, *hm, *w;
    cudaGetSymbolAddress((void**)&xb, g_xb);
    cudaGetSymbolAddress((void**)&aggh, g_aggh);
    cudaGetSymbolAddress((void**)&h1b, g_h1b);
    cudaGetSymbolAddress((void**)&h2b, g_h2b);
    cudaGetSymbolAddress((void**)&hm, g_hm);
    cudaGetSymbolAddress((void**)&w, g_w);

    cudaFuncSetAttribute(k_gemm_mma, cudaFuncAttributeMaxDynamicSharedMemorySize, SMEM_GEMM);

    // fused converts: 160 weight blocks + 6250 x blocks
    k_convert<<<160 + (N_NODES * DF / 8 + 255) / 256, 256>>>(W1l, W1r, W2l, W2r, Wm1, x);

    // CSR build
    k_init<<<(N_NODES + 255) / 256, 256>>>(edge);
    k_count<<<(N_EDGES + 255) / 256, 256>>>(edge);
    k_scanA<<<49, 1024>>>();
    k_scanB<<<1, 64>>>();
    k_scanC<<<49, 1024>>>();
    k_fill<<<(N_EDGES + 255) / 256, 256>>>(edge);

    int aggBlocks = (N_NODES * 32 + 255) / 256;
    dim3 gg((N_NODES + 127) / 128, 4);

    // layer 1
    k_aggregate<<<aggBlocks, 256>>>(xb, aggh);
    k_gemm_mma<<<gg, 256, SMEM_GEMM>>>(aggh, w + 0 * DF * DF, xb, w + 1 * DF * DF,
                                       b1, h1b, N_NODES, 1, 1);

    // layer 2
    k_aggregate<<<aggBlocks, 256>>>(h1b, aggh);
    k_gemm_mma<<<gg, 256, SMEM_GEMM>>>(aggh, w + 2 * DF * DF, h1b, w + 3 * DF * DF,
                                       b2, h2b, N_NODES, 1, 1);

    // MLP hidden (fp16 out)
    k_gemm_mma<<<gg, 256, SMEM_GEMM>>>(h2b, w + 4 * DF * DF, nullptr, w + 4 * DF * DF,
                                       bm1, hm, N_NODES, 0, 1);

    // decoder + softmax
    k_decoder<<<(N_NODES + 3) / 4, 128>>>(hm, Wm2, bm2, out);
}

// round 14
// speedup vs baseline: 1.6736x; 1.0170x over previous
#include <cuda_runtime.h>
#include <cuda_fp16.h>
#include <cstdint>

#define N_NODES 50000
#define N_EDGES 800000
#define DF 256

// ---------------- device scratch ----------------
__device__ int    g_is64;
__device__ int    g_deg[N_NODES];
__device__ int    g_cursor[N_NODES];
__device__ int    g_rowstart[N_NODES + 1];
__device__ int    g_blocksum[64];
__device__ int    g_nbr[N_EDGES];
__device__ __half g_xb[(size_t)N_NODES * DF];
__device__ __half g_aggh[(size_t)N_NODES * DF];
__device__ __half g_h1b[(size_t)N_NODES * DF];
__device__ __half g_h2b[(size_t)N_NODES * DF];
__device__ __half g_hm[(size_t)N_NODES * DF];
__device__ __half g_w[5][DF * DF];

__device__ __forceinline__ int edge_at(const void* edge, int idx) {
    if (g_is64) return (int)((const long long*)edge)[idx];
    return ((const int*)edge)[idx];
}

// ---------------- helpers ----------------
__device__ __forceinline__ uint32_t s2u(const void* p) {
    uint32_t a;
    asm("{ .reg .u64 t; cvta.to.shared.u64 t, %1; cvt.u32.u64 %0, t; }" : "=r"(a) : "l"(p));
    return a;
}
__device__ __forceinline__ uint32_t pack_f16(float a, float b) {
    __half2 h = __floats2half2_rn(a, b);
    return *reinterpret_cast<uint32_t*>(&h);
}

// ---- fused: weight fp16 convert + x fp16 convert + CSR init + dtype detect ----
// blocks [0,160): 5 weight matrices. [160,160+6250): x rows. [6410, 6410+196): init.
#define XBLK ((N_NODES * DF / 8 + 255) / 256)
#define IBLK ((N_NODES + 255) / 256)
__global__ void k_convert(const float* __restrict__ w0, const float* __restrict__ w1,
                          const float* __restrict__ w2, const float* __restrict__ w3,
                          const float* __restrict__ w4, const float* __restrict__ x,
                          const void* edge) {
    int b = blockIdx.x;
    if (b >= 160 + XBLK) {
        int i = (b - 160 - XBLK) * blockDim.x + threadIdx.x;
        if (i < N_NODES) { g_deg[i] = 0; g_cursor[i] = 0; }
        if (i == 0) {
            const long long* e = (const long long*)edge;
            int ok = 1;
            for (int j = 0; j < 16; j++) {
                long long v = e[j];
                if (v < 0 || v >= (long long)N_NODES) ok = 0;
            }
            g_is64 = ok;
        }
        return;
    }
    const float* src;
    uint4* dst;
    int i;
    if (b < 160) {
        int m = b >> 5;
        i = (b & 31) * blockDim.x + threadIdx.x;
        src = (m == 0) ? w0 : (m == 1) ? w1 : (m == 2) ? w2 : (m == 3) ? w3 : w4;
        dst = (uint4*)g_w[m];
    } else {
        i = (b - 160) * blockDim.x + threadIdx.x;
        if (i >= N_NODES * DF / 8) return;
        src = x;
        dst = (uint4*)g_xb;
    }
    const float4* p = (const float4*)src + (size_t)i * 2;
    float4 v0 = __ldg(p), v1 = __ldg(p + 1);
    uint4 o;
    o.x = pack_f16(v0.x, v0.y); o.y = pack_f16(v0.z, v0.w);
    o.z = pack_f16(v1.x, v1.y); o.w = pack_f16(v1.z, v1.w);
    dst[i] = o;
}

// ---------------- CSR build ----------------
__global__ void k_count(const void* __restrict__ edge) {
    int e = blockIdx.x * blockDim.x + threadIdx.x;
    if (e >= N_EDGES) return;
    int dst = edge_at(edge, N_EDGES + e);
    atomicAdd(&g_deg[dst], 1);
}

__global__ void k_scanA() {
    __shared__ int ws[32];
    int b = blockIdx.x, t = threadIdx.x, lane = t & 31, w = t >> 5;
    int i = b * 1024 + t;
    int v = (i < N_NODES) ? g_deg[i] : 0;
    int sv = v;
    #pragma unroll
    for (int off = 1; off < 32; off <<= 1) {
        int x = __shfl_up_sync(0xffffffffu, sv, off);
        if (lane >= off) sv += x;
    }
    if (lane == 31) ws[w] = sv;
    __syncthreads();
    if (w == 0) {
        int s = ws[lane];
        #pragma unroll
        for (int off = 1; off < 32; off <<= 1) {
            int x = __shfl_up_sync(0xffffffffu, s, off);
            if (lane >= off) s += x;
        }
        ws[lane] = s;
    }
    __syncthreads();
    int tot = sv + ((w > 0) ? ws[w - 1] : 0);
    if (i < N_NODES) g_rowstart[i + 1] = tot;
    if (t == 1023) g_blocksum[b] = tot;
    if (b == 0 && t == 0) g_rowstart[0] = 0;
}

// merged scanB+scanC: each block locally prefixes the 49 block sums, applies offset
__global__ void k_scanBC() {
    __shared__ int soff;
    int b = blockIdx.x, t = threadIdx.x;
    if (t == 0) {
        int acc = 0;
        for (int j = 0; j < b; j++) acc += g_blocksum[j];
        soff = acc;
    }
    __syncthreads();
    int i = b * 1024 + t;
    if (i < N_NODES) g_rowstart[i + 1] += soff;
}

__global__ void k_fill(const void* __restrict__ edge) {
    int e = blockIdx.x * blockDim.x + threadIdx.x;
    if (e >= N_EDGES) return;
    int src = edge_at(edge, e);
    int dst = edge_at(edge, N_EDGES + e);
    int p = atomicAdd(&g_cursor[dst], 1);
    g_nbr[g_rowstart[dst] + p] = src;
}

// ---------------- mean aggregation: warp per node, fp16, 8-edge unroll ----------------
__global__ void k_aggregate(const __half* __restrict__ Xb, __half* __restrict__ Oh) {
    int gw = (blockIdx.x * blockDim.x + threadIdx.x) >> 5;
    int lane = threadIdx.x & 31;
    if (gw >= N_NODES) return;
    int s = g_rowstart[gw], e = g_rowstart[gw + 1];
    float acc[8] = {0.f, 0.f, 0.f, 0.f, 0.f, 0.f, 0.f, 0.f};
    int j = s;
    for (; j + 8 <= e; j += 8) {
        uint4 u[8];
        #pragma unroll
        for (int k = 0; k < 8; k++) {
            int sk = g_nbr[j + k];
            u[k] = __ldg((const uint4*)(Xb + (size_t)sk * DF) + lane);
        }
        #pragma unroll
        for (int k = 0; k < 8; k++) {
            const __half2* p = (const __half2*)&u[k];
            #pragma unroll
            for (int i = 0; i < 4; i++) {
                float2 a = __half22float2(p[i]);
                acc[2 * i]     += a.x;
                acc[2 * i + 1] += a.y;
            }
        }
    }
    for (; j + 2 <= e; j += 2) {
        int s0 = g_nbr[j], s1 = g_nbr[j + 1];
        uint4 u0 = __ldg((const uint4*)(Xb + (size_t)s0 * DF) + lane);
        uint4 u1 = __ldg((const uint4*)(Xb + (size_t)s1 * DF) + lane);
        const __half2* p0 = (const __half2*)&u0;
        const __half2* p1 = (const __half2*)&u1;
        #pragma unroll
        for (int i = 0; i < 4; i++) {
            float2 a = __half22float2(p0[i]);
            float2 b = __half22float2(p1[i]);
            acc[2 * i]     += a.x + b.x;
            acc[2 * i + 1] += a.y + b.y;
        }
    }
    if (j < e) {
        int s0 = g_nbr[j];
        uint4 u = __ldg((const uint4*)(Xb + (size_t)s0 * DF) + lane);
        const __half2* up = (const __half2*)&u;
        #pragma unroll
        for (int i = 0; i < 4; i++) {
            float2 a = __half22float2(up[i]);
            acc[2 * i]     += a.x;
            acc[2 * i + 1] += a.y;
        }
    }
    int cnt = e - s;
    float inv = 1.0f / (float)(cnt > 1 ? cnt : 1);
    uint4 o;
    o.x = pack_f16(acc[0] * inv, acc[1] * inv);
    o.y = pack_f16(acc[2] * inv, acc[3] * inv);
    o.z = pack_f16(acc[4] * inv, acc[5] * inv);
    o.w = pack_f16(acc[6] * inv, acc[7] * inv);
    ((uint4*)(Oh + (size_t)gw * DF))[lane] = o;
}

// ======================= pure fp16 mma.sync GEMM =======================
// C = relu?( A1 @ W1^T [+ A2 @ W2^T] + bias ). All operands fp16, fp32 acc.
// CTA 128(M) x 64(N), chunk K=32, double-buffered smem, 2 CTAs/SM.  [R6 structure]

#define S_A 0
#define S_B 10240
#define S_BUF 15360
#define SMEM_GEMM (2 * S_BUF)

__device__ __forceinline__ void ldsm_x4(uint32_t* r, uint32_t addr) {
    asm volatile("ldmatrix.sync.aligned.m8n8.x4.shared.b16 {%0,%1,%2,%3}, [%4];"
                 : "=r"(r[0]), "=r"(r[1]), "=r"(r[2]), "=r"(r[3]) : "r"(addr));
}
__device__ __forceinline__ void mma16816(float* d, const uint32_t* a, uint32_t b0, uint32_t b1) {
    asm volatile(
        "mma.sync.aligned.m16n8k16.row.col.f32.f16.f16.f32 "
        "{%0,%1,%2,%3}, {%4,%5,%6,%7}, {%8,%9}, {%0,%1,%2,%3};"
        : "+f"(d[0]), "+f"(d[1]), "+f"(d[2]), "+f"(d[3])
        : "r"(a[0]), "r"(a[1]), "r"(a[2]), "r"(a[3]), "r"(b0), "r"(b1));
}

__global__ void __launch_bounds__(256, 2) k_gemm_mma(
    const __half* __restrict__ A1, const __half* __restrict__ W1,
    const __half* __restrict__ A2, const __half* __restrict__ W2,
    const float* __restrict__ bias,
    __half* __restrict__ Ch,
    int M, int dual, int relu)
{
    extern __shared__ __align__(16) char smem[];
    uint32_t sb = s2u(smem);
    int tid = threadIdx.x, lane = tid & 31, wid = tid >> 5;
    int bm = blockIdx.x * 128, bn = blockIdx.y * 64;
    int wm = wid & 3, wn = wid >> 2;

    float acc[2][4][4];
    #pragma unroll
    for (int mt = 0; mt < 2; mt++)
        #pragma unroll
        for (int nt = 0; nt < 4; nt++)
            #pragma unroll
            for (int j = 0; j < 4; j++) acc[mt][nt][j] = 0.f;

    int nc = dual ? 16 : 8;
    uint4 av[2], bv;
    int b_n = tid >> 2, b_q = tid & 3;

    auto gload = [&](int c) {
        const __half* A = (c >= 8) ? A2 : A1;
        const __half* B = (c >= 8) ? W2 : W1;
        int kk = (c & 7) * 32;
        #pragma unroll
        for (int i = 0; i < 2; i++) {
            int f = tid + i * 256, row = f >> 2, q = f & 3;
            int grow = bm + row;
            av[i] = (grow < M) ? __ldg((const uint4*)(A + (size_t)grow * DF + kk) + q)
                               : make_uint4(0u, 0u, 0u, 0u);
        }
        bv = __ldg((const uint4*)(B + (size_t)(bn + b_n) * DF + kk) + b_q);
    };

    auto sstore = [&](int buf) {
        char* st = smem + buf * S_BUF;
        #pragma unroll
        for (int i = 0; i < 2; i++) {
            int f = tid + i * 256, row = f >> 2, q = f & 3;
            *(uint4*)(st + S_A + row * 80 + q * 16) = av[i];
        }
        *(uint4*)(st + S_B + b_n * 80 + b_q * 16) = bv;
    };

    gload(0);
    sstore(0);
    __syncthreads();

    for (int c = 0; c < nc; c++) {
        int buf = c & 1;
        if (c + 1 < nc) gload(c + 1);

        uint32_t base = sb + buf * S_BUF;
        int a_row = wm * 32 + (lane & 15);
        int a_col = (lane >> 4) << 3;
        int b_row0 = wn * 32 + (lane & 7) + ((lane >> 4) << 3);
        int b_col = ((lane >> 3) & 1) << 3;

        #pragma unroll
        for (int ks = 0; ks < 2; ks++) {
            int kh = ks * 16;
            uint32_t ah[8], bh[8];
            #pragma unroll
            for (int mt = 0; mt < 2; mt++) {
                uint32_t ad = base + S_A + (a_row + mt * 16) * 80 + (kh + a_col) * 2;
                ldsm_x4(ah + mt * 4, ad);
            }
            #pragma unroll
            for (int h = 0; h < 2; h++) {
                uint32_t bd = base + S_B + (b_row0 + h * 16) * 80 + (kh + b_col) * 2;
                ldsm_x4(bh + h * 4, bd);
            }
            #pragma unroll
            for (int mt = 0; mt < 2; mt++)
                #pragma unroll
                for (int nt = 0; nt < 4; nt++)
                    mma16816(acc[mt][nt], ah + mt * 4, bh[nt * 2], bh[nt * 2 + 1]);
        }
        if (c + 1 < nc) sstore((c + 1) & 1);
        __syncthreads();
    }

    // ---- epilogue: bias + relu; write fp16 ----
    int g = lane >> 2, tg = lane & 3;
    #pragma unroll
    for (int mt = 0; mt < 2; mt++) {
        int r0 = bm + wm * 32 + mt * 16 + g;
        #pragma unroll
        for (int nt = 0; nt < 4; nt++) {
            int col = bn + wn * 32 + nt * 8 + tg * 2;
            float bx = __ldg(bias + col), by = __ldg(bias + col + 1);
            float2 v0, v1;
            v0.x = acc[mt][nt][0] + bx; v0.y = acc[mt][nt][1] + by;
            v1.x = acc[mt][nt][2] + bx; v1.y = acc[mt][nt][3] + by;
            if (relu) {
                v0.x = fmaxf(v0.x, 0.f); v0.y = fmaxf(v0.y, 0.f);
                v1.x = fmaxf(v1.x, 0.f); v1.y = fmaxf(v1.y, 0.f);
            }
            if (r0 < M)
                *(uint32_t*)(Ch + (size_t)r0 * DF + col) = pack_f16(v0.x, v0.y);
            if (r0 + 8 < M)
                *(uint32_t*)(Ch + (size_t)(r0 + 8) * DF + col) = pack_f16(v1.x, v1.y);
        }
    }
}

// ---------------- decoder: logits (8) + softmax, warp per node (fp16 input) -----
__global__ void __launch_bounds__(128) k_decoder(
    const __half* __restrict__ H, const float* __restrict__ Wm2,
    const float* __restrict__ bm2, float* __restrict__ out)
{
    __shared__ float sW[8 * 256];
    int tid = threadIdx.x;
    #pragma unroll
    for (int i = 0; i < 16; i++) sW[tid + i * 128] = Wm2[tid + i * 128];
    __syncthreads();

    int lane = tid & 31, w = tid >> 5;
    int node = blockIdx.x * 4 + w;
    if (node >= N_NODES) return;

    float acc[8] = {0.f, 0.f, 0.f, 0.f, 0.f, 0.f, 0.f, 0.f};
    #pragma unroll
    for (int j = 0; j < 4; j++) {
        __half2 h2v = *(const __half2*)(H + (size_t)node * DF + j * 64 + lane * 2);
        float2 v = __half22float2(h2v);
        #pragma unroll
        for (int o = 0; o < 8; o++) {
            acc[o] = fmaf(v.x, sW[o * 256 + j * 64 + lane * 2], acc[o]);
            acc[o] = fmaf(v.y, sW[o * 256 + j * 64 + lane * 2 + 1], acc[o]);
        }
    }
    #pragma unroll
    for (int o = 0; o < 8; o++)
        #pragma unroll
        for (int off = 16; off >= 1; off >>= 1)
            acc[o] += __shfl_xor_sync(0xffffffffu, acc[o], off);

    if (lane < 8) {
        float logit = acc[lane] + bm2[lane];
        float m = logit;
        #pragma unroll
        for (int off = 4; off >= 1; off >>= 1)
            m = fmaxf(m, __shfl_xor_sync(0xffu, m, off));
        float ex = expf(logit - m);
        float ssum = ex;
        #pragma unroll
        for (int off = 4; off >= 1; off >>= 1)
            ssum += __shfl_xor_sync(0xffu, ssum, off);
        out[(size_t)node * 8 + lane] = ex / ssum;
    }
}

// ---------------- launch ----------------
extern "C" void kernel_launch(void* const* d_in, const int* in_sizes, int n_in,
                              void* d_out, int out_size) {
    const float* x    = (const float*)d_in[0];
    const void*  edge = d_in[1];
    const float* W1l = (const float*)d_in[2];
    const float* b1  = (const float*)d_in[3];
    const float* W1r = (const float*)d_in[4];
    const float* W2l = (const float*)d_in[5];
    const float* b2  = (const float*)d_in[6];
    const float* W2r = (const float*)d_in[7];
    const float* Wm1 = (const float*)d_in[8];
    const float* bm1 = (const float*)d_in[9];
    const float* Wm2 = (const float*)d_in[10];
    const float* bm2 = (const float*)d_in[11];
    float* out = (float*)d_out;

    __half *xb, *aggh, *h1b, *h2b, *hm, *w;
    cudaGetSymbolAddress((void**)&xb, g_xb);
    cudaGetSymbolAddress((void**)&aggh, g_aggh);
    cudaGetSymbolAddress((void**)&h1b, g_h1b);
    cudaGetSymbolAddress((void**)&h2b, g_h2b);
    cudaGetSymbolAddress((void**)&hm, g_hm);
    cudaGetSymbolAddress((void**)&w, g_w);

    cudaFuncSetAttribute(k_gemm_mma, cudaFuncAttributeMaxDynamicSharedMemorySize, SMEM_GEMM);

    // fused converts + CSR init + dtype detect
    k_convert<<<160 + XBLK + IBLK, 256>>>(W1l, W1r, W2l, W2r, Wm1, x, edge);

    // CSR build
    k_count<<<(N_EDGES + 255) / 256, 256>>>(edge);
    k_scanA<<<49, 1024>>>();
    k_scanBC<<<49, 1024>>>();
    k_fill<<<(N_EDGES + 255) / 256, 256>>>(edge);

    int aggBlocks = (N_NODES * 32 + 255) / 256;
    dim3 gg((N_NODES + 127) / 128, 4);

    // layer 1
    k_aggregate<<<aggBlocks, 256>>>(xb, aggh);
    k_gemm_mma<<<gg, 256, SMEM_GEMM>>>(aggh, w + 0 * DF * DF, xb, w + 1 * DF * DF,
                                       b1, h1b, N_NODES, 1, 1);

    // layer 2
    k_aggregate<<<aggBlocks, 256>>>(h1b, aggh);
    k_gemm_mma<<<gg, 256, SMEM_GEMM>>>(aggh, w + 2 * DF * DF, h1b, w + 3 * DF * DF,
                                       b2, h2b, N_NODES, 1, 1);

    // MLP hidden (fp16 out)
    k_gemm_mma<<<gg, 256, SMEM_GEMM>>>(h2b, w + 4 * DF * DF, nullptr, w + 4 * DF * DF,
                                       bm1, hm, N_NODES, 0, 1);

    // decoder + softmax
    k_decoder<<<(N_NODES + 3) / 4, 128>>>(hm, Wm2, bm2, out);
}